// round 2
// baseline (speedup 1.0000x reference)
#include <cuda_runtime.h>
#include <stdint.h>

#define NN 50000
#define EE 400000
#define DD 512
#define HH 512
#define OO 256
#define KK 512
#define BN_EPS 1e-5f

// ---------------- scratch (device globals: allocation-free) ----------------
__device__ float g_X[(size_t)NN * DD];   // layer input activations
__device__ float g_S[(size_t)NN * DD];   // x + aggregated neighbors
__device__ float g_Hb[(size_t)NN * HH];  // hidden after gemm1+relu
__device__ float g_Y[(size_t)NN * HH];   // gemm2 out, pre-BN
__device__ int   g_rowptr[NN + 1];
__device__ int   g_cnt[NN];
__device__ int   g_colidx[EE];
__device__ float g_stats[2 * HH];        // col sums, col sumsq
__device__ float g_mv[2 * HH];           // folded scale, shift

typedef unsigned long long ull;

__device__ __forceinline__ ull ffma2(ull a, ull b, ull c) {
    ull d;
    asm("fma.rn.f32x2 %0, %1, %2, %3;" : "=l"(d) : "l"(a), "l"(b), "l"(c));
    return d;
}
__device__ __forceinline__ ull pack2(float x) {
    ull d;
    unsigned r = __float_as_uint(x);
    asm("mov.b64 %0, {%1, %1};" : "=l"(d) : "r"(r));
    return d;
}

union F4U { float4 f; ull u[2]; float s[4]; };

// ---------------- CSR build ----------------
__global__ void zero_cnt_k() {
    int i = blockIdx.x * blockDim.x + threadIdx.x;
    if (i < NN) g_cnt[i] = 0;
}

__global__ void count_deg_k(const int* __restrict__ ei) {
    int e = blockIdx.x * blockDim.x + threadIdx.x;
    if (e < EE) atomicAdd(&g_cnt[__ldg(ei + EE + e)], 1);
}

__global__ void scan_k() {
    __shared__ int sm[1024];
    int t = threadIdx.x;
    const int CH = (NN + 1023) / 1024;  // 49
    int base = t * CH;
    int s = 0;
    for (int i = 0; i < CH; i++) {
        int idx = base + i;
        if (idx < NN) s += g_cnt[idx];
    }
    sm[t] = s;
    __syncthreads();
    for (int off = 1; off < 1024; off <<= 1) {
        int v = 0;
        if (t >= off) v = sm[t - off];
        __syncthreads();
        if (t >= off) sm[t] += v;
        __syncthreads();
    }
    int run = (t == 0) ? 0 : sm[t - 1];
    for (int i = 0; i < CH; i++) {
        int idx = base + i;
        if (idx < NN) {
            g_rowptr[idx] = run;
            run += g_cnt[idx];
        }
    }
    if (t == 1023) g_rowptr[NN] = run;
}

__global__ void fill_col_k(const int* __restrict__ ei) {
    int e = blockIdx.x * blockDim.x + threadIdx.x;
    if (e < EE) {
        int dst = __ldg(ei + EE + e);
        int pos = g_rowptr[dst] + atomicAdd(&g_cnt[dst], 1);
        g_colidx[pos] = __ldg(ei + e);
    }
}

// ---------------- gather / aggregation ----------------
__global__ void gather_k(const int* __restrict__ idx, const float* __restrict__ emb) {
    int node = blockIdx.x;
    int c = threadIdx.x << 2;
    *(float4*)(g_X + (size_t)node * DD + c) =
        *(const float4*)(emb + (size_t)__ldg(idx + node) * DD + c);
}

__global__ void agg_k() {
    int node = blockIdx.x;
    int c = threadIdx.x << 2;
    float4 acc = *(const float4*)(g_X + (size_t)node * DD + c);
    int pe = g_rowptr[node + 1];
    for (int p = g_rowptr[node]; p < pe; ++p) {
        int s = g_colidx[p];
        const float4 v = *(const float4*)(g_X + (size_t)s * DD + c);
        acc.x += v.x; acc.y += v.y; acc.z += v.z; acc.w += v.w;
    }
    *(float4*)(g_S + (size_t)node * DD + c) = acc;
}

// ---------------- GEMM (128x128x32 tiles, f32x2 FMA) ----------------
template <bool RELU, bool STATS>
__global__ void __launch_bounds__(256, 1) gemm_k(
    const float* __restrict__ A, const float* __restrict__ B,
    const float* __restrict__ bias, float* __restrict__ C, int M, int Ncols)
{
    __shared__ float As[128][36];
    __shared__ float Bs[32][128];

    const int tid = threadIdx.x;
    const int tx = tid & 15, ty = tid >> 4;
    const int aRow = tid >> 3;
    const int aCol = (tid & 7) << 2;
    const int bRow = tid >> 5;
    const int bCol = (tid & 31) << 2;
    const int mBase = blockIdx.y * 128;
    const int nBase = blockIdx.x * 128;

    float4 aReg[4], bReg[4];
#pragma unroll
    for (int i = 0; i < 4; i++) {
        int r = mBase + aRow + 32 * i;
        aReg[i] = (r < M) ? *(const float4*)(A + (size_t)r * KK + aCol)
                          : make_float4(0.f, 0.f, 0.f, 0.f);
    }
#pragma unroll
    for (int i = 0; i < 4; i++)
        bReg[i] = *(const float4*)(B + (size_t)(bRow + 8 * i) * Ncols + nBase + bCol);

    ull acc[8][4];
#pragma unroll
    for (int i = 0; i < 8; i++)
#pragma unroll
        for (int j = 0; j < 4; j++) acc[i][j] = 0ull;

    const int NT = KK / 32;
    for (int kt = 0; kt < NT; kt++) {
        __syncthreads();
#pragma unroll
        for (int i = 0; i < 4; i++) *(float4*)&As[aRow + 32 * i][aCol] = aReg[i];
#pragma unroll
        for (int i = 0; i < 4; i++) *(float4*)&Bs[bRow + 8 * i][bCol] = bReg[i];
        __syncthreads();

        if (kt + 1 < NT) {
            int kb = (kt + 1) * 32;
#pragma unroll
            for (int i = 0; i < 4; i++) {
                int r = mBase + aRow + 32 * i;
                aReg[i] = (r < M) ? *(const float4*)(A + (size_t)r * KK + kb + aCol)
                                  : make_float4(0.f, 0.f, 0.f, 0.f);
            }
#pragma unroll
            for (int i = 0; i < 4; i++)
                bReg[i] = *(const float4*)(B + (size_t)(kb + bRow + 8 * i) * Ncols + nBase + bCol);
        }

#pragma unroll
        for (int k = 0; k < 32; k++) {
            F4U b0, b1;
            b0.f = *(const float4*)&Bs[k][tx * 8];
            b1.f = *(const float4*)&Bs[k][tx * 8 + 4];
#pragma unroll
            for (int i = 0; i < 8; i++) {
                ull ap = pack2(As[ty * 8 + i][k]);
                acc[i][0] = ffma2(ap, b0.u[0], acc[i][0]);
                acc[i][1] = ffma2(ap, b0.u[1], acc[i][1]);
                acc[i][2] = ffma2(ap, b1.u[0], acc[i][2]);
                acc[i][3] = ffma2(ap, b1.u[1], acc[i][3]);
            }
        }
    }

    // ---- epilogue: bias (+stats) (+relu) ----
    F4U bi0, bi1;
    bi0.f = *(const float4*)(bias + nBase + tx * 8);
    bi1.f = *(const float4*)(bias + nBase + tx * 8 + 4);

    float ls[8], lsq[8];
#pragma unroll
    for (int j = 0; j < 8; j++) { ls[j] = 0.f; lsq[j] = 0.f; }

#pragma unroll
    for (int i = 0; i < 8; i++) {
        int r = mBase + ty * 8 + i;
        if (r < M) {
            F4U o0, o1;
            o0.u[0] = acc[i][0]; o0.u[1] = acc[i][1];
            o1.u[0] = acc[i][2]; o1.u[1] = acc[i][3];
#pragma unroll
            for (int j = 0; j < 4; j++) { o0.s[j] += bi0.s[j]; o1.s[j] += bi1.s[j]; }
            if (STATS) {
#pragma unroll
                for (int j = 0; j < 4; j++) {
                    ls[j] += o0.s[j];     lsq[j] += o0.s[j] * o0.s[j];
                    ls[4 + j] += o1.s[j]; lsq[4 + j] += o1.s[j] * o1.s[j];
                }
            }
            if (RELU) {
#pragma unroll
                for (int j = 0; j < 4; j++) {
                    o0.s[j] = fmaxf(o0.s[j], 0.f);
                    o1.s[j] = fmaxf(o1.s[j], 0.f);
                }
            }
            *(float4*)(C + (size_t)r * Ncols + nBase + tx * 8) = o0.f;
            *(float4*)(C + (size_t)r * Ncols + nBase + tx * 8 + 4) = o1.f;
        }
    }

    if (STATS) {
        float* red = &As[0][0];  // 4608 floats available, need 2048
        __syncthreads();
#pragma unroll
        for (int j = 0; j < 8; j++) red[ty * 128 + tx * 8 + j] = ls[j];
        __syncthreads();
        if (tid < 128) {
            float s = 0.f;
#pragma unroll
            for (int t = 0; t < 16; t++) s += red[t * 128 + tid];
            atomicAdd(&g_stats[nBase + tid], s);
        }
        __syncthreads();
#pragma unroll
        for (int j = 0; j < 8; j++) red[ty * 128 + tx * 8 + j] = lsq[j];
        __syncthreads();
        if (tid < 128) {
            float s = 0.f;
#pragma unroll
            for (int t = 0; t < 16; t++) s += red[t * 128 + tid];
            atomicAdd(&g_stats[HH + nBase + tid], s);
        }
    }
}

// ---------------- BN ----------------
__global__ void zero_stats_k() {
    int i = threadIdx.x;
    g_stats[i] = 0.f;
    g_stats[HH + i] = 0.f;
}

__global__ void finalize_k(const float* __restrict__ gam, const float* __restrict__ bet) {
    int c = threadIdx.x;
    float mu = g_stats[c] * (1.f / NN);
    float var = g_stats[HH + c] * (1.f / NN) - mu * mu;
    float sc = rsqrtf(var + BN_EPS) * gam[c];
    g_mv[c] = sc;
    g_mv[HH + c] = bet[c] - mu * sc;
}

__global__ void bnrelu_k() {
    int i = blockIdx.x * blockDim.x + threadIdx.x;
    if (i >= NN * HH / 4) return;
    int c = (i << 2) & (HH - 1);
    float4 y = *(const float4*)(g_Y + (size_t)i * 4);
    float4 o;
    o.x = fmaxf(fmaf(y.x, g_mv[c],     g_mv[HH + c]),     0.f);
    o.y = fmaxf(fmaf(y.y, g_mv[c + 1], g_mv[HH + c + 1]), 0.f);
    o.z = fmaxf(fmaf(y.z, g_mv[c + 2], g_mv[HH + c + 2]), 0.f);
    o.w = fmaxf(fmaf(y.w, g_mv[c + 3], g_mv[HH + c + 3]), 0.f);
    *(float4*)(g_X + (size_t)i * 4) = o;
}

// ---------------- driver ----------------
extern "C" void kernel_launch(void* const* d_in, const int* in_sizes, int n_in,
                              void* d_out, int out_size) {
    const int*   xi  = (const int*)d_in[0];
    const int*   ei  = (const int*)d_in[1];
    const float* emb = (const float*)d_in[2];
    const float* w1[3] = {(const float*)d_in[3], (const float*)d_in[9],  (const float*)d_in[15]};
    const float* b1[3] = {(const float*)d_in[4], (const float*)d_in[10], (const float*)d_in[16]};
    const float* w2[3] = {(const float*)d_in[5], (const float*)d_in[11], (const float*)d_in[17]};
    const float* b2[3] = {(const float*)d_in[6], (const float*)d_in[12], (const float*)d_in[18]};
    const float* gam[2] = {(const float*)d_in[7], (const float*)d_in[13]};
    const float* bet[2] = {(const float*)d_in[8], (const float*)d_in[14]};

    float *pS, *pH, *pY;
    cudaGetSymbolAddress((void**)&pS, g_S);
    cudaGetSymbolAddress((void**)&pH, g_Hb);
    cudaGetSymbolAddress((void**)&pY, g_Y);

    // CSR build (once per call; reused by all 3 layers)
    zero_cnt_k<<<(NN + 255) / 256, 256>>>();
    count_deg_k<<<(EE + 255) / 256, 256>>>(ei);
    scan_k<<<1, 1024>>>();
    zero_cnt_k<<<(NN + 255) / 256, 256>>>();
    fill_col_k<<<(EE + 255) / 256, 256>>>(ei);

    gather_k<<<NN, 128>>>(xi, emb);

    dim3 g512(HH / 128, (NN + 127) / 128);
    dim3 g256(OO / 128, (NN + 127) / 128);

    for (int l = 0; l < 3; ++l) {
        agg_k<<<NN, 128>>>();
        gemm_k<true, false><<<g512, 256>>>(pS, w1[l], b1[l], pH, NN, HH);
        if (l < 2) {
            zero_stats_k<<<1, HH>>>();
            gemm_k<false, true><<<g512, 256>>>(pH, w2[l], b2[l], pY, NN, HH);
            finalize_k<<<1, HH>>>(gam[l], bet[l]);
            bnrelu_k<<<(NN * HH / 4 + 255) / 256, 256>>>();
        } else {
            gemm_k<false, false><<<g256, 256>>>(pH, w2[2], b2[2], (float*)d_out, NN, OO);
        }
    }
}

// round 4
// speedup vs baseline: 2.1785x; 2.1785x over previous
#include <cuda_runtime.h>
#include <cuda_bf16.h>
#include <stdint.h>

#define NN 50000
#define EE 400000
#define HH 512
#define OO 256
#define KK 512
#define BN_EPS 1e-5f

#define BM 128
#define BNT 128          // N tile
#define NCH 48           // 3 segments * 16 chunks of K=32

// ---------------- scratch (device globals) ----------------
__device__ __align__(256) float g_X[(size_t)NN * KK];
__device__ __align__(256) float g_Y[(size_t)NN * HH];
__device__ __align__(256) __nv_bfloat16 g_Shi[(size_t)NN * KK];
__device__ __align__(256) __nv_bfloat16 g_Slo[(size_t)NN * KK];
__device__ __align__(256) __nv_bfloat16 g_Hhi[(size_t)NN * HH];
__device__ __align__(256) __nv_bfloat16 g_Hlo[(size_t)NN * HH];
__device__ __align__(256) __nv_bfloat16 g_WtA_hi[KK * HH], g_WtA_lo[KK * HH];
__device__ __align__(256) __nv_bfloat16 g_WtB_hi[KK * HH], g_WtB_lo[KK * HH];
__device__ int   g_rowptr[NN + 1];
__device__ int   g_cnt[NN];
__device__ int   g_colidx[EE];
__device__ float g_stats[2 * HH];
__device__ float g_mv[2 * HH];

// ---------------- PTX helpers (all sm_80-level, sm_100-safe) ----------------
__device__ __forceinline__ uint32_t smem_u32(const void* p) {
    uint32_t a;
    asm("{ .reg .u64 t; cvta.to.shared.u64 t, %1; cvt.u32.u64 %0, t; }" : "=r"(a) : "l"(p));
    return a;
}
__device__ __forceinline__ uint32_t sw64(uint32_t b) { return b ^ ((b >> 3) & 0x30); }

__device__ __forceinline__ void cpa16(uint32_t dst, const void* src, bool pred) {
    int sz = pred ? 16 : 0;
    asm volatile("cp.async.cg.shared.global [%0], [%1], 16, %2;"
                 :: "r"(dst), "l"(src), "r"(sz) : "memory");
}
__device__ __forceinline__ void cpa_commit() {
    asm volatile("cp.async.commit_group;" ::: "memory");
}
template <int N>
__device__ __forceinline__ void cpa_wait() {
    asm volatile("cp.async.wait_group %0;" :: "n"(N) : "memory");
}
__device__ __forceinline__ void ldmx4(uint32_t* r, uint32_t addr) {
    asm volatile("ldmatrix.sync.aligned.m8n8.x4.shared.b16 {%0,%1,%2,%3}, [%4];"
                 : "=r"(r[0]), "=r"(r[1]), "=r"(r[2]), "=r"(r[3]) : "r"(addr));
}
__device__ __forceinline__ void mma16816(float* c, const uint32_t* a, const uint32_t* b) {
    asm volatile(
        "mma.sync.aligned.m16n8k16.row.col.f32.bf16.bf16.f32 "
        "{%0,%1,%2,%3},{%4,%5,%6,%7},{%8,%9},{%0,%1,%2,%3};"
        : "+f"(c[0]), "+f"(c[1]), "+f"(c[2]), "+f"(c[3])
        : "r"(a[0]), "r"(a[1]), "r"(a[2]), "r"(a[3]), "r"(b[0]), "r"(b[1]));
}

// ---------------- CSR build ----------------
__global__ void zero_cnt_k() {
    int i = blockIdx.x * blockDim.x + threadIdx.x;
    if (i < NN) g_cnt[i] = 0;
}
__global__ void count_deg_k(const int* __restrict__ ei) {
    int e = blockIdx.x * blockDim.x + threadIdx.x;
    if (e < EE) atomicAdd(&g_cnt[__ldg(ei + EE + e)], 1);
}
__global__ void scan_k() {
    __shared__ int sm[1024];
    int t = threadIdx.x;
    const int CH = (NN + 1023) / 1024;
    int base = t * CH;
    int s = 0;
    for (int i = 0; i < CH; i++) {
        int idx = base + i;
        if (idx < NN) s += g_cnt[idx];
    }
    sm[t] = s;
    __syncthreads();
    for (int off = 1; off < 1024; off <<= 1) {
        int v = 0;
        if (t >= off) v = sm[t - off];
        __syncthreads();
        if (t >= off) sm[t] += v;
        __syncthreads();
    }
    int run = (t == 0) ? 0 : sm[t - 1];
    for (int i = 0; i < CH; i++) {
        int idx = base + i;
        if (idx < NN) {
            g_rowptr[idx] = run;
            run += g_cnt[idx];
        }
    }
    if (t == 1023) g_rowptr[NN] = run;
}
__global__ void fill_col_k(const int* __restrict__ ei) {
    int e = blockIdx.x * blockDim.x + threadIdx.x;
    if (e < EE) {
        int dst = __ldg(ei + EE + e);
        int pos = g_rowptr[dst] + atomicAdd(&g_cnt[dst], 1);
        g_colidx[pos] = __ldg(ei + e);
    }
}

// ---------------- gather / agg / bn ----------------
__global__ void gather_k(const int* __restrict__ idx, const float* __restrict__ emb) {
    int node = blockIdx.x;
    int c = threadIdx.x << 2;
    *(float4*)(g_X + (size_t)node * KK + c) =
        *(const float4*)(emb + (size_t)__ldg(idx + node) * KK + c);
}

__device__ __forceinline__ void split2(float a, float b, uint32_t& hi, uint32_t& lo) {
    __nv_bfloat16 ha = __float2bfloat16(a), hb = __float2bfloat16(b);
    float ra = a - __bfloat162float(ha), rb = b - __bfloat162float(hb);
    __nv_bfloat162 hp, lp;
    hp.x = ha; hp.y = hb;
    lp.x = __float2bfloat16(ra); lp.y = __float2bfloat16(rb);
    hi = *(uint32_t*)&hp; lo = *(uint32_t*)&lp;
}

__global__ void agg_k() {
    int node = blockIdx.x;
    int c = threadIdx.x << 2;
    float4 acc = *(const float4*)(g_X + (size_t)node * KK + c);
    int pe = g_rowptr[node + 1];
    for (int p = g_rowptr[node]; p < pe; ++p) {
        int s = g_colidx[p];
        const float4 v = *(const float4*)(g_X + (size_t)s * KK + c);
        acc.x += v.x; acc.y += v.y; acc.z += v.z; acc.w += v.w;
    }
    uint2 hv, lv;
    split2(acc.x, acc.y, hv.x, lv.x);
    split2(acc.z, acc.w, hv.y, lv.y);
    *(uint2*)(g_Shi + (size_t)node * KK + c) = hv;
    *(uint2*)(g_Slo + (size_t)node * KK + c) = lv;
}

__global__ void zero_stats_k() {
    int i = threadIdx.x;
    g_stats[i] = 0.f;
    g_stats[HH + i] = 0.f;
}
#define SROWS 250
__global__ void stats_k() {
    int c = threadIdx.x;           // handles cols c and c+256
    int r0 = blockIdx.x * SROWS;
    int r1 = r0 + SROWS;
    if (r1 > NN) r1 = NN;
    float s0 = 0.f, q0 = 0.f, s1 = 0.f, q1 = 0.f;
    for (int r = r0; r < r1; r++) {
        float v0 = g_Y[(size_t)r * HH + c];
        float v1 = g_Y[(size_t)r * HH + c + 256];
        s0 += v0; q0 += v0 * v0;
        s1 += v1; q1 += v1 * v1;
    }
    atomicAdd(&g_stats[c], s0);
    atomicAdd(&g_stats[HH + c], q0);
    atomicAdd(&g_stats[c + 256], s1);
    atomicAdd(&g_stats[HH + c + 256], q1);
}
__global__ void finalize_k(const float* __restrict__ gam, const float* __restrict__ bet) {
    int c = threadIdx.x;
    float mu = g_stats[c] * (1.f / NN);
    float var = g_stats[HH + c] * (1.f / NN) - mu * mu;
    float sc = rsqrtf(var + BN_EPS) * gam[c];
    g_mv[c] = sc;
    g_mv[HH + c] = bet[c] - mu * sc;
}
__global__ void bnrelu_k() {
    int i = blockIdx.x * blockDim.x + threadIdx.x;
    if (i >= NN * HH / 4) return;
    int c = (i << 2) & (HH - 1);
    float4 y = *(const float4*)(g_Y + (size_t)i * 4);
    float4 o;
    o.x = fmaxf(fmaf(y.x, g_mv[c],     g_mv[HH + c]),     0.f);
    o.y = fmaxf(fmaf(y.y, g_mv[c + 1], g_mv[HH + c + 1]), 0.f);
    o.z = fmaxf(fmaf(y.z, g_mv[c + 2], g_mv[HH + c + 2]), 0.f);
    o.w = fmaxf(fmaf(y.w, g_mv[c + 3], g_mv[HH + c + 3]), 0.f);
    *(float4*)(g_X + (size_t)i * 4) = o;
}

// ---------------- weight transpose + bf16 split ----------------
__global__ void wsplit_k(const float* __restrict__ w, __nv_bfloat16* __restrict__ th,
                         __nv_bfloat16* __restrict__ tl, int Ndim) {
    __shared__ float t[32][33];
    int bx = blockIdx.x * 32;  // k
    int by = blockIdx.y * 32;  // n
    int x = threadIdx.x, y = threadIdx.y;
#pragma unroll
    for (int i = 0; i < 32; i += 8)
        t[y + i][x] = w[(size_t)(bx + y + i) * Ndim + by + x];
    __syncthreads();
#pragma unroll
    for (int i = 0; i < 32; i += 8) {
        float v = t[x][y + i];
        __nv_bfloat16 h = __float2bfloat16(v);
        float lo = v - __bfloat162float(h);
        th[(size_t)(by + y + i) * KK + bx + x] = h;
        tl[(size_t)(by + y + i) * KK + bx + x] = __float2bfloat16(lo);
    }
}

// ---------------- mma.sync GEMM ----------------
__device__ __forceinline__ void load_tiles(
    uint32_t sa, uint32_t sb,
    const __nv_bfloat16* __restrict__ A, const __nv_bfloat16* __restrict__ W,
    int mBase, int M, int nBase, int kk, int tid)
{
#pragma unroll
    for (int i = 0; i < 2; i++) {
        int idx = i * 256 + tid;
        int row = idx >> 2, cu = idx & 3;
        int grow = mBase + row;
        const char* src = (const char*)(A + (size_t)grow * KK + kk) + cu * 16;
        cpa16(sa + sw64(row * 64 + cu * 16), src, grow < M);
    }
#pragma unroll
    for (int i = 0; i < 2; i++) {
        int idx = i * 256 + tid;
        int row = idx >> 2, cu = idx & 3;
        const char* src = (const char*)(W + (size_t)(nBase + row) * KK + kk) + cu * 16;
        cpa16(sb + sw64(row * 64 + cu * 16), src, true);
    }
}

// MODE 0: bias+relu -> bf16 hi/lo ; MODE 1: bias -> fp32 ; MODE 2: bias -> fp32 (out)
template <int MODE>
__global__ void __launch_bounds__(256) gemm_mma(
    const __nv_bfloat16* __restrict__ Ahi, const __nv_bfloat16* __restrict__ Alo,
    const __nv_bfloat16* __restrict__ Whi, const __nv_bfloat16* __restrict__ Wlo,
    const float* __restrict__ bias,
    float* __restrict__ Cf,
    __nv_bfloat16* __restrict__ Chi, __nv_bfloat16* __restrict__ Clo,
    int M, int Ncols)
{
    __shared__ __align__(1024) uint8_t smem[3 * 16384];  // 3 stages x (A 8K + B 8K)
    uint32_t sbase = smem_u32(smem);

    const int tid = threadIdx.x, lane = tid & 31, wid = tid >> 5;
    const int wm = wid >> 1, wn = wid & 1;
    const int mBase = blockIdx.y * BM;
    const int nBase = blockIdx.x * BNT;

    float acc[2][8][4];
#pragma unroll
    for (int a = 0; a < 2; a++)
#pragma unroll
        for (int b = 0; b < 8; b++)
#pragma unroll
            for (int c = 0; c < 4; c++) acc[a][b][c] = 0.f;

    // chunk kc: segment = kc/16 -> (Ahi,Whi),(Ahi,Wlo),(Alo,Whi); kk = (kc%16)*32
#define SEG_A(kc) (((kc) < 32) ? Ahi : Alo)
#define SEG_W(kc) ((((kc) >= 16) && ((kc) < 32)) ? Wlo : Whi)

    // prologue: stages 0,1
    load_tiles(sbase, sbase + 8192, SEG_A(0), SEG_W(0), mBase, M, nBase, 0, tid);
    cpa_commit();
    load_tiles(sbase + 16384, sbase + 16384 + 8192, SEG_A(1), SEG_W(1),
               mBase, M, nBase, 32, tid);
    cpa_commit();

    for (int kc = 0; kc < NCH; kc++) {
        int buf = kc % 3;
        if (kc + 2 < NCH) {
            int nb = (kc + 2) % 3;
            load_tiles(sbase + nb * 16384, sbase + nb * 16384 + 8192,
                       SEG_A(kc + 2), SEG_W(kc + 2), mBase, M, nBase,
                       ((kc + 2) & 15) * 32, tid);
            cpa_commit();
            cpa_wait<2>();
        } else {
            cpa_wait<0>();
        }
        __syncthreads();

        uint32_t aT = sbase + buf * 16384;
        uint32_t bT = aT + 8192;
#pragma unroll
        for (int k16 = 0; k16 < 2; k16++) {
            uint32_t aF[2][4];
#pragma unroll
            for (int fm = 0; fm < 2; fm++) {
                int row = wm * 32 + fm * 16 + (lane & 15);
                int cu = 2 * k16 + (lane >> 4);
                ldmx4(aF[fm], aT + sw64(row * 64 + cu * 16));
            }
            uint32_t bF[4][4];
#pragma unroll
            for (int g = 0; g < 4; g++) {
                int half = (lane >> 3) & 1;
                int sel = lane >> 4;
                int row = wn * 64 + g * 16 + sel * 8 + (lane & 7);
                int cu = 2 * k16 + half;
                ldmx4(bF[g], bT + sw64(row * 64 + cu * 16));
            }
#pragma unroll
            for (int fm = 0; fm < 2; fm++)
#pragma unroll
                for (int fn = 0; fn < 8; fn++)
                    mma16816(acc[fm][fn], aF[fm], &bF[fn >> 1][(fn & 1) * 2]);
        }
        __syncthreads();
    }

    // ---- epilogue ----
#pragma unroll
    for (int fn = 0; fn < 8; fn++) {
        int col = nBase + wn * 64 + fn * 8 + (lane & 3) * 2;
        float bv0 = __ldg(bias + col);
        float bv1 = __ldg(bias + col + 1);
#pragma unroll
        for (int fm = 0; fm < 2; fm++) {
            int rowb = mBase + wm * 32 + fm * 16 + (lane >> 2);
            float* a = acc[fm][fn];
#pragma unroll
            for (int h = 0; h < 2; h++) {
                int r = rowb + 8 * h;
                if (r < M) {
                    float v0 = a[2 * h] + bv0, v1 = a[2 * h + 1] + bv1;
                    if (MODE == 0) {
                        v0 = fmaxf(v0, 0.f);
                        v1 = fmaxf(v1, 0.f);
                        __nv_bfloat16 h0 = __float2bfloat16(v0);
                        __nv_bfloat16 h1 = __float2bfloat16(v1);
                        __nv_bfloat162 hp, lp;
                        hp.x = h0; hp.y = h1;
                        lp.x = __float2bfloat16(v0 - __bfloat162float(h0));
                        lp.y = __float2bfloat16(v1 - __bfloat162float(h1));
                        *(__nv_bfloat162*)(Chi + (size_t)r * Ncols + col) = hp;
                        *(__nv_bfloat162*)(Clo + (size_t)r * Ncols + col) = lp;
                    } else {
                        float2 o; o.x = v0; o.y = v1;
                        *(float2*)(Cf + (size_t)r * Ncols + col) = o;
                    }
                }
            }
        }
    }
}

// ---------------- driver ----------------
extern "C" void kernel_launch(void* const* d_in, const int* in_sizes, int n_in,
                              void* d_out, int out_size) {
    const int*   xi  = (const int*)d_in[0];
    const int*   ei  = (const int*)d_in[1];
    const float* emb = (const float*)d_in[2];
    const float* w1[3] = {(const float*)d_in[3], (const float*)d_in[9],  (const float*)d_in[15]};
    const float* b1[3] = {(const float*)d_in[4], (const float*)d_in[10], (const float*)d_in[16]};
    const float* w2[3] = {(const float*)d_in[5], (const float*)d_in[11], (const float*)d_in[17]};
    const float* b2[3] = {(const float*)d_in[6], (const float*)d_in[12], (const float*)d_in[18]};
    const float* gam[2] = {(const float*)d_in[7], (const float*)d_in[13]};
    const float* bet[2] = {(const float*)d_in[8], (const float*)d_in[14]};

    __nv_bfloat16 *pShi, *pSlo, *pHhi, *pHlo, *pWAh, *pWAl, *pWBh, *pWBl;
    float *pY;
    cudaGetSymbolAddress((void**)&pShi, g_Shi);
    cudaGetSymbolAddress((void**)&pSlo, g_Slo);
    cudaGetSymbolAddress((void**)&pHhi, g_Hhi);
    cudaGetSymbolAddress((void**)&pHlo, g_Hlo);
    cudaGetSymbolAddress((void**)&pWAh, g_WtA_hi);
    cudaGetSymbolAddress((void**)&pWAl, g_WtA_lo);
    cudaGetSymbolAddress((void**)&pWBh, g_WtB_hi);
    cudaGetSymbolAddress((void**)&pWBl, g_WtB_lo);
    cudaGetSymbolAddress((void**)&pY, g_Y);

    // CSR build
    zero_cnt_k<<<(NN + 255) / 256, 256>>>();
    count_deg_k<<<(EE + 255) / 256, 256>>>(ei);
    scan_k<<<1, 1024>>>();
    zero_cnt_k<<<(NN + 255) / 256, 256>>>();
    fill_col_k<<<(EE + 255) / 256, 256>>>(ei);

    gather_k<<<NN, 128>>>(xi, emb);

    dim3 tb(32, 8);
    dim3 gw512(KK / 32, 512 / 32);
    dim3 gw256(KK / 32, 256 / 32);
    dim3 gg512(512 / BNT, (NN + BM - 1) / BM);
    dim3 gg256(256 / BNT, (NN + BM - 1) / BM);

    for (int l = 0; l < 3; ++l) {
        wsplit_k<<<gw512, tb>>>(w1[l], pWAh, pWAl, 512);
        agg_k<<<NN, 128>>>();
        gemm_mma<0><<<gg512, 256>>>(pShi, pSlo, pWAh, pWAl, b1[l],
                                    nullptr, pHhi, pHlo, NN, 512);
        if (l < 2) {
            wsplit_k<<<gw512, tb>>>(w2[l], pWBh, pWBl, 512);
            gemm_mma<1><<<gg512, 256>>>(pHhi, pHlo, pWBh, pWBl, b2[l],
                                        pY, nullptr, nullptr, NN, 512);
            zero_stats_k<<<1, HH>>>();
            stats_k<<<(NN + SROWS - 1) / SROWS, 256>>>();
            finalize_k<<<1, HH>>>(gam[l], bet[l]);
            bnrelu_k<<<(NN * HH / 4 + 255) / 256, 256>>>();
        } else {
            wsplit_k<<<gw256, tb>>>(w2[2], pWBh, pWBl, 256);
            gemm_mma<2><<<gg256, 256>>>(pHhi, pHlo, pWBh, pWBl, b2[2],
                                        (float*)d_out, nullptr, nullptr, NN, 256);
        }
    }
}

// round 7
// speedup vs baseline: 2.2031x; 1.0113x over previous
#include <cuda_runtime.h>
#include <cuda_bf16.h>
#include <stdint.h>

#define NN 50000
#define EE 400000
#define HH 512
#define OO 256
#define KK 512
#define BN_EPS 1e-5f

#define BM 128
#define BNT 128          // N tile
#define NCH 48           // 3 segments * 16 chunks of K=32

// ---------------- scratch (device globals) ----------------
__device__ __align__(256) float g_Y[(size_t)NN * HH];
__device__ __align__(256) __nv_bfloat16 g_Shi[(size_t)NN * KK];
__device__ __align__(256) __nv_bfloat16 g_Slo[(size_t)NN * KK];
__device__ __align__(256) __nv_bfloat16 g_Hhi[(size_t)NN * HH];
__device__ __align__(256) __nv_bfloat16 g_Hlo[(size_t)NN * HH];
__device__ __align__(256) __nv_bfloat16 g_Wh[3][KK * HH], g_Wl[3][KK * HH];  // w1 splits [N][K]
__device__ __align__(256) __nv_bfloat16 g_Vh[3][KK * HH], g_Vl[3][KK * HH];  // w2 splits
__device__ int   g_rowptr[NN + 1];
__device__ int   g_cnt[NN];
__device__ int   g_colidx[EE];
__device__ float g_stats[2 * HH];
__device__ float g_mv[2 * HH];

// ---------------- PTX helpers (sm_80-level, sm_100-safe) ----------------
__device__ __forceinline__ uint32_t smem_u32(const void* p) {
    uint32_t a;
    asm("{ .reg .u64 t; cvta.to.shared.u64 t, %1; cvt.u32.u64 %0, t; }" : "=r"(a) : "l"(p));
    return a;
}
__device__ __forceinline__ uint32_t sw64(uint32_t b) { return b ^ ((b >> 3) & 0x30); }

__device__ __forceinline__ void cpa16(uint32_t dst, const void* src, bool pred) {
    int sz = pred ? 16 : 0;
    asm volatile("cp.async.cg.shared.global [%0], [%1], 16, %2;"
                 :: "r"(dst), "l"(src), "r"(sz) : "memory");
}
__device__ __forceinline__ void cpa_commit() {
    asm volatile("cp.async.commit_group;" ::: "memory");
}
template <int N>
__device__ __forceinline__ void cpa_wait() {
    asm volatile("cp.async.wait_group %0;" :: "n"(N) : "memory");
}
__device__ __forceinline__ void ldmx4(uint32_t* r, uint32_t addr) {
    asm volatile("ldmatrix.sync.aligned.m8n8.x4.shared.b16 {%0,%1,%2,%3}, [%4];"
                 : "=r"(r[0]), "=r"(r[1]), "=r"(r[2]), "=r"(r[3]) : "r"(addr));
}
__device__ __forceinline__ void mma16816(float* c, const uint32_t* a, const uint32_t* b) {
    asm volatile(
        "mma.sync.aligned.m16n8k16.row.col.f32.bf16.bf16.f32 "
        "{%0,%1,%2,%3},{%4,%5,%6,%7},{%8,%9},{%0,%1,%2,%3};"
        : "+f"(c[0]), "+f"(c[1]), "+f"(c[2]), "+f"(c[3])
        : "r"(a[0]), "r"(a[1]), "r"(a[2]), "r"(a[3]), "r"(b[0]), "r"(b[1]));
}

// ---------------- CSR build ----------------
__global__ void zero_cnt_k() {
    int i = blockIdx.x * blockDim.x + threadIdx.x;
    if (i < NN) g_cnt[i] = 0;
}
__global__ void count_deg_k(const int* __restrict__ ei) {
    int e = blockIdx.x * blockDim.x + threadIdx.x;
    if (e < EE) atomicAdd(&g_cnt[__ldg(ei + EE + e)], 1);
}
__global__ void scan_k() {
    __shared__ int sm[1024];
    int t = threadIdx.x;
    const int CH = (NN + 1023) / 1024;
    int base = t * CH;
    int s = 0;
    for (int i = 0; i < CH; i++) {
        int idx = base + i;
        if (idx < NN) s += g_cnt[idx];
    }
    sm[t] = s;
    __syncthreads();
    for (int off = 1; off < 1024; off <<= 1) {
        int v = 0;
        if (t >= off) v = sm[t - off];
        __syncthreads();
        if (t >= off) sm[t] += v;
        __syncthreads();
    }
    int run = (t == 0) ? 0 : sm[t - 1];
    for (int i = 0; i < CH; i++) {
        int idx = base + i;
        if (idx < NN) {
            g_rowptr[idx] = run;
            run += g_cnt[idx];
        }
    }
    if (t == 1023) g_rowptr[NN] = run;
}
__global__ void fill_col_k(const int* __restrict__ ei) {
    int e = blockIdx.x * blockDim.x + threadIdx.x;
    if (e < EE) {
        int dst = __ldg(ei + EE + e);
        int pos = g_rowptr[dst] + atomicAdd(&g_cnt[dst], 1);
        g_colidx[pos] = __ldg(ei + e);
    }
}

// ---------------- fused aggregation ----------------
__device__ __forceinline__ void split2(float a, float b, uint32_t& hi, uint32_t& lo) {
    __nv_bfloat16 ha = __float2bfloat16(a), hb = __float2bfloat16(b);
    float ra = a - __bfloat162float(ha), rb = b - __bfloat162float(hb);
    __nv_bfloat162 hp, lp;
    hp.x = ha; hp.y = hb;
    lp.x = __float2bfloat16(ra); lp.y = __float2bfloat16(rb);
    hi = *(uint32_t*)&hp; lo = *(uint32_t*)&lp;
}

__device__ __forceinline__ void store_split(int node, int c, const float4& acc) {
    uint2 hv, lv;
    split2(acc.x, acc.y, hv.x, lv.x);
    split2(acc.z, acc.w, hv.y, lv.y);
    *(uint2*)(g_Shi + (size_t)node * KK + c) = hv;
    *(uint2*)(g_Slo + (size_t)node * KK + c) = lv;
}

// layer 0: S = emb[xi[node]] + sum emb[xi[src]]
__global__ void agg_emb_k(const int* __restrict__ xi, const float* __restrict__ emb) {
    __shared__ int snb[128];
    int node = blockIdx.x;
    int tid = threadIdx.x;
    int c = tid << 2;
    float4 acc = *(const float4*)(emb + (size_t)__ldg(xi + node) * KK + c);
    int ps = g_rowptr[node], pe = g_rowptr[node + 1];
    for (int base = ps; base < pe; base += 128) {
        int n = min(128, pe - base);
        __syncthreads();
        if (tid < n) snb[tid] = __ldg(xi + __ldg(g_colidx + base + tid));
        __syncthreads();
        for (int j = 0; j < n; j++) {
            const float4 v = *(const float4*)(emb + (size_t)snb[j] * KK + c);
            acc.x += v.x; acc.y += v.y; acc.z += v.z; acc.w += v.w;
        }
    }
    store_split(node, c, acc);
}

// layers 1,2: x = relu(bn(Y)) applied on the fly; S = x[node] + sum x[src]
__global__ void agg_bn_k() {
    __shared__ int snb[128];
    int node = blockIdx.x;
    int tid = threadIdx.x;
    int c = tid << 2;
    float4 sc = *(const float4*)(g_mv + c);
    float4 sh = *(const float4*)(g_mv + HH + c);
    const float4* Y4 = (const float4*)g_Y;
    float4 y = Y4[((size_t)node * KK + c) >> 2];
    float4 acc;
    acc.x = fmaxf(fmaf(y.x, sc.x, sh.x), 0.f);
    acc.y = fmaxf(fmaf(y.y, sc.y, sh.y), 0.f);
    acc.z = fmaxf(fmaf(y.z, sc.z, sh.z), 0.f);
    acc.w = fmaxf(fmaf(y.w, sc.w, sh.w), 0.f);
    int ps = g_rowptr[node], pe = g_rowptr[node + 1];
    for (int base = ps; base < pe; base += 128) {
        int n = min(128, pe - base);
        __syncthreads();
        if (tid < n) snb[tid] = __ldg(g_colidx + base + tid);
        __syncthreads();
        for (int j = 0; j < n; j++) {
            float4 v = Y4[((size_t)snb[j] * KK + c) >> 2];
            acc.x += fmaxf(fmaf(v.x, sc.x, sh.x), 0.f);
            acc.y += fmaxf(fmaf(v.y, sc.y, sh.y), 0.f);
            acc.z += fmaxf(fmaf(v.z, sc.z, sh.z), 0.f);
            acc.w += fmaxf(fmaf(v.w, sc.w, sh.w), 0.f);
        }
    }
    store_split(node, c, acc);
}

// ---------------- BN stats ----------------
__global__ void zero_stats_k() {
    int i = threadIdx.x;
    g_stats[i] = 0.f;
    g_stats[HH + i] = 0.f;
}
#define SROWS 250
__global__ void stats_k() {
    int c = threadIdx.x;
    int r0 = blockIdx.x * SROWS;
    int r1 = min(r0 + SROWS, NN);
    float s0 = 0.f, q0 = 0.f, s1 = 0.f, q1 = 0.f;
    for (int r = r0; r < r1; r++) {
        float v0 = g_Y[(size_t)r * HH + c];
        float v1 = g_Y[(size_t)r * HH + c + 256];
        s0 += v0; q0 += v0 * v0;
        s1 += v1; q1 += v1 * v1;
    }
    atomicAdd(&g_stats[c], s0);
    atomicAdd(&g_stats[HH + c], q0);
    atomicAdd(&g_stats[c + 256], s1);
    atomicAdd(&g_stats[HH + c + 256], q1);
}
__global__ void finalize_k(const float* __restrict__ gam, const float* __restrict__ bet) {
    int c = threadIdx.x;
    float mu = g_stats[c] * (1.f / NN);
    float var = g_stats[HH + c] * (1.f / NN) - mu * mu;
    float sc = rsqrtf(var + BN_EPS) * gam[c];
    g_mv[c] = sc;
    g_mv[HH + c] = bet[c] - mu * sc;
}

// ---------------- weight transpose + bf16 split ----------------
__global__ void wsplit_k(const float* __restrict__ w, __nv_bfloat16* __restrict__ th,
                         __nv_bfloat16* __restrict__ tl, int Ndim) {
    __shared__ float t[32][33];
    int bx = blockIdx.x * 32;  // k
    int by = blockIdx.y * 32;  // n
    int x = threadIdx.x, y = threadIdx.y;
#pragma unroll
    for (int i = 0; i < 32; i += 8)
        t[y + i][x] = w[(size_t)(bx + y + i) * Ndim + by + x];
    __syncthreads();
#pragma unroll
    for (int i = 0; i < 32; i += 8) {
        float v = t[x][y + i];
        __nv_bfloat16 h = __float2bfloat16(v);
        float lo = v - __bfloat162float(h);
        th[(size_t)(by + y + i) * KK + bx + x] = h;
        tl[(size_t)(by + y + i) * KK + bx + x] = __float2bfloat16(lo);
    }
}

// ---------------- mma.sync GEMM (BK=32, static 48KB smem, 3-stage) ----------------
__device__ __forceinline__ void load_tiles(
    uint32_t sa, uint32_t sb,
    const __nv_bfloat16* __restrict__ A, const __nv_bfloat16* __restrict__ W,
    int mBase, int M, int nBase, int kk, int tid)
{
#pragma unroll
    for (int i = 0; i < 2; i++) {
        int idx = i * 256 + tid;
        int row = idx >> 2, cu = idx & 3;
        int grow = mBase + row;
        const char* src = (const char*)(A + (size_t)grow * KK + kk) + cu * 16;
        cpa16(sa + sw64(row * 64 + cu * 16), src, grow < M);
    }
#pragma unroll
    for (int i = 0; i < 2; i++) {
        int idx = i * 256 + tid;
        int row = idx >> 2, cu = idx & 3;
        const char* src = (const char*)(W + (size_t)(nBase + row) * KK + kk) + cu * 16;
        cpa16(sb + sw64(row * 64 + cu * 16), src, true);
    }
}

// MODE 0: bias+relu -> bf16 hi/lo ; MODE 1: bias -> fp32 Y ; MODE 2: bias -> fp32 out
template <int MODE>
__global__ void __launch_bounds__(256) gemm_mma(
    const __nv_bfloat16* __restrict__ Ahi, const __nv_bfloat16* __restrict__ Alo,
    const __nv_bfloat16* __restrict__ Whi, const __nv_bfloat16* __restrict__ Wlo,
    const float* __restrict__ bias,
    float* __restrict__ Cf,
    __nv_bfloat16* __restrict__ Chi, __nv_bfloat16* __restrict__ Clo,
    int M, int Ncols)
{
    __shared__ __align__(1024) uint8_t smem[3 * 16384];  // 3 stages x (A 8K + B 8K)
    uint32_t sbase = smem_u32(smem);

    const int tid = threadIdx.x, lane = tid & 31, wid = tid >> 5;
    const int wm = wid >> 1, wn = wid & 1;
    const int mBase = blockIdx.y * BM;
    const int nBase = blockIdx.x * BNT;

    float acc[2][8][4];
#pragma unroll
    for (int a = 0; a < 2; a++)
#pragma unroll
        for (int b = 0; b < 8; b++)
#pragma unroll
            for (int c = 0; c < 4; c++) acc[a][b][c] = 0.f;

    // chunk kc: segment = kc/16 -> (Ahi,Whi),(Ahi,Wlo),(Alo,Whi); kk = (kc%16)*32
#define SEG_A(kc) (((kc) < 32) ? Ahi : Alo)
#define SEG_W(kc) ((((kc) >= 16) && ((kc) < 32)) ? Wlo : Whi)

    load_tiles(sbase, sbase + 8192, SEG_A(0), SEG_W(0), mBase, M, nBase, 0, tid);
    cpa_commit();
    load_tiles(sbase + 16384, sbase + 16384 + 8192, SEG_A(1), SEG_W(1),
               mBase, M, nBase, 32, tid);
    cpa_commit();

    for (int kc = 0; kc < NCH; kc++) {
        int buf = kc % 3;
        if (kc + 2 < NCH) {
            int nb = (kc + 2) % 3;
            load_tiles(sbase + nb * 16384, sbase + nb * 16384 + 8192,
                       SEG_A(kc + 2), SEG_W(kc + 2), mBase, M, nBase,
                       ((kc + 2) & 15) * 32, tid);
            cpa_commit();
            cpa_wait<2>();
        } else {
            cpa_wait<0>();
        }
        __syncthreads();

        uint32_t aT = sbase + buf * 16384;
        uint32_t bT = aT + 8192;
#pragma unroll
        for (int k16 = 0; k16 < 2; k16++) {
            uint32_t aF[2][4];
#pragma unroll
            for (int fm = 0; fm < 2; fm++) {
                int row = wm * 32 + fm * 16 + (lane & 15);
                int cu = 2 * k16 + (lane >> 4);
                ldmx4(aF[fm], aT + sw64(row * 64 + cu * 16));
            }
            uint32_t bF[4][4];
#pragma unroll
            for (int g = 0; g < 4; g++) {
                int half = (lane >> 3) & 1;
                int sel = lane >> 4;
                int row = wn * 64 + g * 16 + sel * 8 + (lane & 7);
                int cu = 2 * k16 + half;
                ldmx4(bF[g], bT + sw64(row * 64 + cu * 16));
            }
#pragma unroll
            for (int fm = 0; fm < 2; fm++)
#pragma unroll
                for (int fn = 0; fn < 8; fn++)
                    mma16816(acc[fm][fn], aF[fm], &bF[fn >> 1][(fn & 1) * 2]);
        }
        __syncthreads();
    }

    // ---- epilogue ----
#pragma unroll
    for (int fn = 0; fn < 8; fn++) {
        int col = nBase + wn * 64 + fn * 8 + (lane & 3) * 2;
        float bv0 = __ldg(bias + col);
        float bv1 = __ldg(bias + col + 1);
#pragma unroll
        for (int fm = 0; fm < 2; fm++) {
            int rowb = mBase + wm * 32 + fm * 16 + (lane >> 2);
            float* a = acc[fm][fn];
#pragma unroll
            for (int h = 0; h < 2; h++) {
                int r = rowb + 8 * h;
                if (r < M) {
                    float v0 = a[2 * h] + bv0, v1 = a[2 * h + 1] + bv1;
                    if (MODE == 0) {
                        v0 = fmaxf(v0, 0.f);
                        v1 = fmaxf(v1, 0.f);
                        __nv_bfloat16 h0 = __float2bfloat16(v0);
                        __nv_bfloat16 h1 = __float2bfloat16(v1);
                        __nv_bfloat162 hp, lp;
                        hp.x = h0; hp.y = h1;
                        lp.x = __float2bfloat16(v0 - __bfloat162float(h0));
                        lp.y = __float2bfloat16(v1 - __bfloat162float(h1));
                        *(__nv_bfloat162*)(Chi + (size_t)r * Ncols + col) = hp;
                        *(__nv_bfloat162*)(Clo + (size_t)r * Ncols + col) = lp;
                    } else {
                        float2 o; o.x = v0; o.y = v1;
                        *(float2*)(Cf + (size_t)r * Ncols + col) = o;
                    }
                }
            }
        }
    }
}

// ---------------- driver ----------------
extern "C" void kernel_launch(void* const* d_in, const int* in_sizes, int n_in,
                              void* d_out, int out_size) {
    const int*   xi  = (const int*)d_in[0];
    const int*   ei  = (const int*)d_in[1];
    const float* emb = (const float*)d_in[2];
    const float* w1[3] = {(const float*)d_in[3], (const float*)d_in[9],  (const float*)d_in[15]};
    const float* b1[3] = {(const float*)d_in[4], (const float*)d_in[10], (const float*)d_in[16]};
    const float* w2[3] = {(const float*)d_in[5], (const float*)d_in[11], (const float*)d_in[17]};
    const float* b2[3] = {(const float*)d_in[6], (const float*)d_in[12], (const float*)d_in[18]};
    const float* gam[2] = {(const float*)d_in[7], (const float*)d_in[13]};
    const float* bet[2] = {(const float*)d_in[8], (const float*)d_in[14]};

    __nv_bfloat16 *pShi, *pSlo, *pHhi, *pHlo, *pWh, *pWl, *pVh, *pVl;
    float *pY;
    cudaGetSymbolAddress((void**)&pShi, g_Shi);
    cudaGetSymbolAddress((void**)&pSlo, g_Slo);
    cudaGetSymbolAddress((void**)&pHhi, g_Hhi);
    cudaGetSymbolAddress((void**)&pHlo, g_Hlo);
    cudaGetSymbolAddress((void**)&pWh, g_Wh);
    cudaGetSymbolAddress((void**)&pWl, g_Wl);
    cudaGetSymbolAddress((void**)&pVh, g_Vh);
    cudaGetSymbolAddress((void**)&pVl, g_Vl);
    cudaGetSymbolAddress((void**)&pY, g_Y);

    dim3 tb(32, 8);
    dim3 gw512(KK / 32, 512 / 32);
    dim3 gw256(KK / 32, 256 / 32);

    // weight splits (independent — front of graph)
    for (int l = 0; l < 3; ++l) {
        wsplit_k<<<gw512, tb>>>(w1[l], pWh + (size_t)l * KK * HH, pWl + (size_t)l * KK * HH, 512);
        if (l < 2)
            wsplit_k<<<gw512, tb>>>(w2[l], pVh + (size_t)l * KK * HH, pVl + (size_t)l * KK * HH, 512);
        else
            wsplit_k<<<gw256, tb>>>(w2[2], pVh + (size_t)2 * KK * HH, pVl + (size_t)2 * KK * HH, 256);
    }

    // CSR build
    zero_cnt_k<<<(NN + 255) / 256, 256>>>();
    count_deg_k<<<(EE + 255) / 256, 256>>>(ei);
    scan_k<<<1, 1024>>>();
    zero_cnt_k<<<(NN + 255) / 256, 256>>>();
    fill_col_k<<<(EE + 255) / 256, 256>>>(ei);

    dim3 gg512(512 / BNT, (NN + BM - 1) / BM);
    dim3 gg256(256 / BNT, (NN + BM - 1) / BM);

    for (int l = 0; l < 3; ++l) {
        if (l == 0) agg_emb_k<<<NN, 128>>>(xi, emb);
        else        agg_bn_k<<<NN, 128>>>();

        gemm_mma<0><<<gg512, 256>>>(pShi, pSlo,
            pWh + (size_t)l * KK * HH, pWl + (size_t)l * KK * HH, b1[l],
            nullptr, pHhi, pHlo, NN, 512);

        if (l < 2) {
            gemm_mma<1><<<gg512, 256>>>(pHhi, pHlo,
                pVh + (size_t)l * KK * HH, pVl + (size_t)l * KK * HH, b2[l],
                pY, nullptr, nullptr, NN, 512);
            zero_stats_k<<<1, HH>>>();
            stats_k<<<(NN + SROWS - 1) / SROWS, 256>>>();
            finalize_k<<<1, HH>>>(gam[l], bet[l]);
        } else {
            gemm_mma<2><<<gg256, 256>>>(pHhi, pHlo,
                pVh + (size_t)2 * KK * HH, pVl + (size_t)2 * KK * HH, b2[2],
                (float*)d_out, nullptr, nullptr, NN, 256);
        }
    }
}

// round 8
// speedup vs baseline: 2.9401x; 1.3345x over previous
#include <cuda_runtime.h>
#include <cuda_fp16.h>
#include <stdint.h>

#define NN 50000
#define EE 400000
#define HH 512
#define OO 256
#define KK 512
#define BN_EPS 1e-5f

#define BM 128
#define BNT 128          // N tile
#define NCH 32           // 2 segments * 16 chunks of K=32

// ---------------- scratch (device globals) ----------------
__device__ __align__(256) float g_Y[(size_t)NN * HH];
__device__ __align__(256) __half g_Sh[(size_t)NN * KK];          // fp16(S)
__device__ __align__(256) __half g_Hh[(size_t)NN * HH];          // fp16(relu(gemm1))
__device__ __align__(256) __half g_Wh[3][KK * HH], g_Wl[3][KK * HH];  // w1 hi/lo [N][K]
__device__ __align__(256) __half g_Vh[3][KK * HH], g_Vl[3][KK * HH];  // w2 hi/lo [N][K]
__device__ int   g_rowptr[NN + 1];
__device__ int   g_cnt[NN];
__device__ int   g_colidx[EE];
__device__ float g_stats[2 * HH];
__device__ float g_mv[2 * HH];

// ---------------- PTX helpers (sm_80-level, sm_100-safe) ----------------
__device__ __forceinline__ uint32_t smem_u32(const void* p) {
    uint32_t a;
    asm("{ .reg .u64 t; cvta.to.shared.u64 t, %1; cvt.u32.u64 %0, t; }" : "=r"(a) : "l"(p));
    return a;
}
__device__ __forceinline__ uint32_t sw64(uint32_t b) { return b ^ ((b >> 3) & 0x30); }

__device__ __forceinline__ void cpa16(uint32_t dst, const void* src, bool pred) {
    int sz = pred ? 16 : 0;
    asm volatile("cp.async.cg.shared.global [%0], [%1], 16, %2;"
                 :: "r"(dst), "l"(src), "r"(sz) : "memory");
}
__device__ __forceinline__ void cpa_commit() {
    asm volatile("cp.async.commit_group;" ::: "memory");
}
template <int N>
__device__ __forceinline__ void cpa_wait() {
    asm volatile("cp.async.wait_group %0;" :: "n"(N) : "memory");
}
__device__ __forceinline__ void ldmx4(uint32_t* r, uint32_t addr) {
    asm volatile("ldmatrix.sync.aligned.m8n8.x4.shared.b16 {%0,%1,%2,%3}, [%4];"
                 : "=r"(r[0]), "=r"(r[1]), "=r"(r[2]), "=r"(r[3]) : "r"(addr));
}
__device__ __forceinline__ void mma16816(float* c, const uint32_t* a, const uint32_t* b) {
    asm volatile(
        "mma.sync.aligned.m16n8k16.row.col.f32.f16.f16.f32 "
        "{%0,%1,%2,%3},{%4,%5,%6,%7},{%8,%9},{%0,%1,%2,%3};"
        : "+f"(c[0]), "+f"(c[1]), "+f"(c[2]), "+f"(c[3])
        : "r"(a[0]), "r"(a[1]), "r"(a[2]), "r"(a[3]), "r"(b[0]), "r"(b[1]));
}

// ---------------- CSR build ----------------
__global__ void zero_cnt_k() {
    int i = blockIdx.x * blockDim.x + threadIdx.x;
    if (i < NN) g_cnt[i] = 0;
}
__global__ void count_deg_k(const int* __restrict__ ei) {
    int e = blockIdx.x * blockDim.x + threadIdx.x;
    if (e < EE) atomicAdd(&g_cnt[__ldg(ei + EE + e)], 1);
}
__global__ void scan_k() {
    __shared__ int sm[1024];
    int t = threadIdx.x;
    const int CH = (NN + 1023) / 1024;
    int base = t * CH;
    int s = 0;
    for (int i = 0; i < CH; i++) {
        int idx = base + i;
        if (idx < NN) s += g_cnt[idx];
    }
    sm[t] = s;
    __syncthreads();
    for (int off = 1; off < 1024; off <<= 1) {
        int v = 0;
        if (t >= off) v = sm[t - off];
        __syncthreads();
        if (t >= off) sm[t] += v;
        __syncthreads();
    }
    int run = (t == 0) ? 0 : sm[t - 1];
    for (int i = 0; i < CH; i++) {
        int idx = base + i;
        if (idx < NN) {
            g_rowptr[idx] = run;
            run += g_cnt[idx];
        }
    }
    if (t == 1023) g_rowptr[NN] = run;
}
__global__ void fill_col_k(const int* __restrict__ ei) {
    int e = blockIdx.x * blockDim.x + threadIdx.x;
    if (e < EE) {
        int dst = __ldg(ei + EE + e);
        int pos = g_rowptr[dst] + atomicAdd(&g_cnt[dst], 1);
        g_colidx[pos] = __ldg(ei + e);
    }
}

// ---------------- fused aggregation ----------------
__device__ __forceinline__ void store_h4(int node, int c, const float4& acc) {
    __half2 h0 = __floats2half2_rn(acc.x, acc.y);
    __half2 h1 = __floats2half2_rn(acc.z, acc.w);
    uint2 v;
    v.x = *(uint32_t*)&h0;
    v.y = *(uint32_t*)&h1;
    *(uint2*)(g_Sh + (size_t)node * KK + c) = v;
}

// layer 0: S = emb[xi[node]] + sum emb[xi[src]]
__global__ void agg_emb_k(const int* __restrict__ xi, const float* __restrict__ emb) {
    __shared__ int snb[128];
    int node = blockIdx.x;
    int tid = threadIdx.x;
    int c = tid << 2;
    float4 acc = *(const float4*)(emb + (size_t)__ldg(xi + node) * KK + c);
    int ps = g_rowptr[node], pe = g_rowptr[node + 1];
    for (int base = ps; base < pe; base += 128) {
        int n = min(128, pe - base);
        __syncthreads();
        if (tid < n) snb[tid] = __ldg(xi + __ldg(g_colidx + base + tid));
        __syncthreads();
        for (int j = 0; j < n; j++) {
            const float4 v = *(const float4*)(emb + (size_t)snb[j] * KK + c);
            acc.x += v.x; acc.y += v.y; acc.z += v.z; acc.w += v.w;
        }
    }
    store_h4(node, c, acc);
}

// layers 1,2: x = relu(bn(Y)) on the fly; S = x[node] + sum x[src]
__global__ void agg_bn_k() {
    __shared__ int snb[128];
    int node = blockIdx.x;
    int tid = threadIdx.x;
    int c = tid << 2;
    float4 sc = *(const float4*)(g_mv + c);
    float4 sh = *(const float4*)(g_mv + HH + c);
    const float4* Y4 = (const float4*)g_Y;
    float4 y = Y4[((size_t)node * KK + c) >> 2];
    float4 acc;
    acc.x = fmaxf(fmaf(y.x, sc.x, sh.x), 0.f);
    acc.y = fmaxf(fmaf(y.y, sc.y, sh.y), 0.f);
    acc.z = fmaxf(fmaf(y.z, sc.z, sh.z), 0.f);
    acc.w = fmaxf(fmaf(y.w, sc.w, sh.w), 0.f);
    int ps = g_rowptr[node], pe = g_rowptr[node + 1];
    for (int base = ps; base < pe; base += 128) {
        int n = min(128, pe - base);
        __syncthreads();
        if (tid < n) snb[tid] = __ldg(g_colidx + base + tid);
        __syncthreads();
        for (int j = 0; j < n; j++) {
            float4 v = Y4[((size_t)snb[j] * KK + c) >> 2];
            acc.x += fmaxf(fmaf(v.x, sc.x, sh.x), 0.f);
            acc.y += fmaxf(fmaf(v.y, sc.y, sh.y), 0.f);
            acc.z += fmaxf(fmaf(v.z, sc.z, sh.z), 0.f);
            acc.w += fmaxf(fmaf(v.w, sc.w, sh.w), 0.f);
        }
    }
    store_h4(node, c, acc);
}

// ---------------- BN stats ----------------
__global__ void zero_stats_k() {
    int i = threadIdx.x;
    g_stats[i] = 0.f;
    g_stats[HH + i] = 0.f;
}
#define SROWS 250
__global__ void stats_k() {
    int c = threadIdx.x;
    int r0 = blockIdx.x * SROWS;
    int r1 = min(r0 + SROWS, NN);
    float s0 = 0.f, q0 = 0.f, s1 = 0.f, q1 = 0.f;
    for (int r = r0; r < r1; r++) {
        float v0 = g_Y[(size_t)r * HH + c];
        float v1 = g_Y[(size_t)r * HH + c + 256];
        s0 += v0; q0 += v0 * v0;
        s1 += v1; q1 += v1 * v1;
    }
    atomicAdd(&g_stats[c], s0);
    atomicAdd(&g_stats[HH + c], q0);
    atomicAdd(&g_stats[c + 256], s1);
    atomicAdd(&g_stats[HH + c + 256], q1);
}
__global__ void finalize_k(const float* __restrict__ gam, const float* __restrict__ bet) {
    int c = threadIdx.x;
    float mu = g_stats[c] * (1.f / NN);
    float var = g_stats[HH + c] * (1.f / NN) - mu * mu;
    float sc = rsqrtf(var + BN_EPS) * gam[c];
    g_mv[c] = sc;
    g_mv[HH + c] = bet[c] - mu * sc;
}

// ---------------- weight transpose + fp16 split ----------------
__global__ void wsplit_k(const float* __restrict__ w, __half* __restrict__ th,
                         __half* __restrict__ tl, int Ndim) {
    __shared__ float t[32][33];
    int bx = blockIdx.x * 32;  // k
    int by = blockIdx.y * 32;  // n
    int x = threadIdx.x, y = threadIdx.y;
#pragma unroll
    for (int i = 0; i < 32; i += 8)
        t[y + i][x] = w[(size_t)(bx + y + i) * Ndim + by + x];
    __syncthreads();
#pragma unroll
    for (int i = 0; i < 32; i += 8) {
        float v = t[x][y + i];
        __half h = __float2half_rn(v);
        float lo = v - __half2float(h);
        th[(size_t)(by + y + i) * KK + bx + x] = h;
        tl[(size_t)(by + y + i) * KK + bx + x] = __float2half_rn(lo);
    }
}

// ---------------- mma.sync GEMM (BK=32, static 48KB smem, 3-stage) ----------------
__device__ __forceinline__ void load_tiles(
    uint32_t sa, uint32_t sb,
    const __half* __restrict__ A, const __half* __restrict__ W,
    int mBase, int M, int nBase, int kk, int tid)
{
#pragma unroll
    for (int i = 0; i < 2; i++) {
        int idx = i * 256 + tid;
        int row = idx >> 2, cu = idx & 3;
        int grow = mBase + row;
        const char* src = (const char*)(A + (size_t)grow * KK + kk) + cu * 16;
        cpa16(sa + sw64(row * 64 + cu * 16), src, grow < M);
    }
#pragma unroll
    for (int i = 0; i < 2; i++) {
        int idx = i * 256 + tid;
        int row = idx >> 2, cu = idx & 3;
        const char* src = (const char*)(W + (size_t)(nBase + row) * KK + kk) + cu * 16;
        cpa16(sb + sw64(row * 64 + cu * 16), src, true);
    }
}

// MODE 0: bias+relu -> fp16 H ; MODE 1: bias -> fp32 Y ; MODE 2: bias -> fp32 out
template <int MODE>
__global__ void __launch_bounds__(256) gemm_mma(
    const __half* __restrict__ Ah,
    const __half* __restrict__ Wh, const __half* __restrict__ Wl,
    const float* __restrict__ bias,
    float* __restrict__ Cf, __half* __restrict__ Ch,
    int M, int Ncols)
{
    __shared__ __align__(1024) uint8_t smem[3 * 16384];  // 3 stages x (A 8K + B 8K)
    uint32_t sbase = smem_u32(smem);

    const int tid = threadIdx.x, lane = tid & 31, wid = tid >> 5;
    const int wm = wid >> 1, wn = wid & 1;
    const int mBase = blockIdx.y * BM;
    const int nBase = blockIdx.x * BNT;

    float acc[2][8][4];
#pragma unroll
    for (int a = 0; a < 2; a++)
#pragma unroll
        for (int b = 0; b < 8; b++)
#pragma unroll
            for (int c = 0; c < 4; c++) acc[a][b][c] = 0.f;

    // chunk kc: segment = kc/16 -> (Ah,Wh),(Ah,Wl); kk = (kc%16)*32
#define SEG_W(kc) (((kc) < 16) ? Wh : Wl)
#define SEG_K(kc) (((kc) & 15) * 32)

    load_tiles(sbase, sbase + 8192, Ah, SEG_W(0), mBase, M, nBase, SEG_K(0), tid);
    cpa_commit();
    load_tiles(sbase + 16384, sbase + 16384 + 8192, Ah, SEG_W(1),
               mBase, M, nBase, SEG_K(1), tid);
    cpa_commit();

    for (int kc = 0; kc < NCH; kc++) {
        int buf = kc % 3;
        if (kc + 2 < NCH) {
            int nb = (kc + 2) % 3;
            load_tiles(sbase + nb * 16384, sbase + nb * 16384 + 8192,
                       Ah, SEG_W(kc + 2), mBase, M, nBase, SEG_K(kc + 2), tid);
            cpa_commit();
            cpa_wait<2>();
        } else {
            cpa_wait<0>();
        }
        __syncthreads();

        uint32_t aT = sbase + buf * 16384;
        uint32_t bT = aT + 8192;
#pragma unroll
        for (int k16 = 0; k16 < 2; k16++) {
            uint32_t aF[2][4];
#pragma unroll
            for (int fm = 0; fm < 2; fm++) {
                int row = wm * 32 + fm * 16 + (lane & 15);
                int cu = 2 * k16 + (lane >> 4);
                ldmx4(aF[fm], aT + sw64(row * 64 + cu * 16));
            }
            uint32_t bF[4][4];
#pragma unroll
            for (int g = 0; g < 4; g++) {
                int half = (lane >> 3) & 1;
                int sel = lane >> 4;
                int row = wn * 64 + g * 16 + sel * 8 + (lane & 7);
                int cu = 2 * k16 + half;
                ldmx4(bF[g], bT + sw64(row * 64 + cu * 16));
            }
#pragma unroll
            for (int fm = 0; fm < 2; fm++)
#pragma unroll
                for (int fn = 0; fn < 8; fn++)
                    mma16816(acc[fm][fn], aF[fm], &bF[fn >> 1][(fn & 1) * 2]);
        }
        __syncthreads();
    }

    // ---- epilogue ----
#pragma unroll
    for (int fn = 0; fn < 8; fn++) {
        int col = nBase + wn * 64 + fn * 8 + (lane & 3) * 2;
        float bv0 = __ldg(bias + col);
        float bv1 = __ldg(bias + col + 1);
#pragma unroll
        for (int fm = 0; fm < 2; fm++) {
            int rowb = mBase + wm * 32 + fm * 16 + (lane >> 2);
            float* a = acc[fm][fn];
#pragma unroll
            for (int h = 0; h < 2; h++) {
                int r = rowb + 8 * h;
                if (r < M) {
                    float v0 = a[2 * h] + bv0, v1 = a[2 * h + 1] + bv1;
                    if (MODE == 0) {
                        v0 = fmaxf(v0, 0.f);
                        v1 = fmaxf(v1, 0.f);
                        __half2 hp = __floats2half2_rn(v0, v1);
                        *(__half2*)(Ch + (size_t)r * Ncols + col) = hp;
                    } else {
                        float2 o; o.x = v0; o.y = v1;
                        *(float2*)(Cf + (size_t)r * Ncols + col) = o;
                    }
                }
            }
        }
    }
}

// ---------------- driver ----------------
extern "C" void kernel_launch(void* const* d_in, const int* in_sizes, int n_in,
                              void* d_out, int out_size) {
    const int*   xi  = (const int*)d_in[0];
    const int*   ei  = (const int*)d_in[1];
    const float* emb = (const float*)d_in[2];
    const float* w1[3] = {(const float*)d_in[3], (const float*)d_in[9],  (const float*)d_in[15]};
    const float* b1[3] = {(const float*)d_in[4], (const float*)d_in[10], (const float*)d_in[16]};
    const float* w2[3] = {(const float*)d_in[5], (const float*)d_in[11], (const float*)d_in[17]};
    const float* b2[3] = {(const float*)d_in[6], (const float*)d_in[12], (const float*)d_in[18]};
    const float* gam[2] = {(const float*)d_in[7], (const float*)d_in[13]};
    const float* bet[2] = {(const float*)d_in[8], (const float*)d_in[14]};

    __half *pSh, *pHh, *pWh, *pWl, *pVh, *pVl;
    float *pY;
    cudaGetSymbolAddress((void**)&pSh, g_Sh);
    cudaGetSymbolAddress((void**)&pHh, g_Hh);
    cudaGetSymbolAddress((void**)&pWh, g_Wh);
    cudaGetSymbolAddress((void**)&pWl, g_Wl);
    cudaGetSymbolAddress((void**)&pVh, g_Vh);
    cudaGetSymbolAddress((void**)&pVl, g_Vl);
    cudaGetSymbolAddress((void**)&pY, g_Y);

    dim3 tb(32, 8);
    dim3 gw512(KK / 32, 512 / 32);
    dim3 gw256(KK / 32, 256 / 32);

    // weight splits (independent — front of graph)
    for (int l = 0; l < 3; ++l) {
        wsplit_k<<<gw512, tb>>>(w1[l], pWh + (size_t)l * KK * HH, pWl + (size_t)l * KK * HH, 512);
        if (l < 2)
            wsplit_k<<<gw512, tb>>>(w2[l], pVh + (size_t)l * KK * HH, pVl + (size_t)l * KK * HH, 512);
        else
            wsplit_k<<<gw256, tb>>>(w2[2], pVh + (size_t)2 * KK * HH, pVl + (size_t)2 * KK * HH, 256);
    }

    // CSR build
    zero_cnt_k<<<(NN + 255) / 256, 256>>>();
    count_deg_k<<<(EE + 255) / 256, 256>>>(ei);
    scan_k<<<1, 1024>>>();
    zero_cnt_k<<<(NN + 255) / 256, 256>>>();
    fill_col_k<<<(EE + 255) / 256, 256>>>(ei);

    dim3 gg512(512 / BNT, (NN + BM - 1) / BM);
    dim3 gg256(256 / BNT, (NN + BM - 1) / BM);

    for (int l = 0; l < 3; ++l) {
        if (l == 0) agg_emb_k<<<NN, 128>>>(xi, emb);
        else        agg_bn_k<<<NN, 128>>>();

        gemm_mma<0><<<gg512, 256>>>(pSh,
            pWh + (size_t)l * KK * HH, pWl + (size_t)l * KK * HH, b1[l],
            nullptr, pHh, NN, 512);

        if (l < 2) {
            gemm_mma<1><<<gg512, 256>>>(pHh,
                pVh + (size_t)l * KK * HH, pVl + (size_t)l * KK * HH, b2[l],
                pY, nullptr, NN, 512);
            zero_stats_k<<<1, HH>>>();
            stats_k<<<(NN + SROWS - 1) / SROWS, 256>>>();
            finalize_k<<<1, HH>>>(gam[l], bet[l]);
        } else {
            gemm_mma<2><<<gg256, 256>>>(pHh,
                pVh + (size_t)2 * KK * HH, pVl + (size_t)2 * KK * HH, b2[2],
                (float*)d_out, nullptr, NN, 256);
        }
    }
}

// round 9
// speedup vs baseline: 3.0947x; 1.0526x over previous
#include <cuda_runtime.h>
#include <cuda_fp16.h>
#include <stdint.h>

#define NN 50000
#define EE 400000
#define HH 512
#define OO 256
#define KK 512
#define BN_EPS 1e-5f

#define BM 128
#define BNT 128          // N tile
#define NCHK 16          // 16 chunks of K=32, both W segments per chunk
#define STG 24576        // stage: A 8KB + Wh 8KB + Wl 8KB

// ---------------- scratch (device globals) ----------------
__device__ __align__(256) float g_Y[(size_t)NN * HH];
__device__ __align__(256) __half g_Sh[(size_t)NN * KK];          // fp16(S)
__device__ __align__(256) __half g_Hh[(size_t)NN * HH];          // fp16(relu(gemm1))
__device__ __align__(256) __half g_Wh[3][KK * HH], g_Wl[3][KK * HH];  // w1 hi/lo [N][K]
__device__ __align__(256) __half g_Vh[3][KK * HH], g_Vl[3][KK * HH];  // w2 hi/lo [N][K]
__device__ int   g_rowptr[NN + 1];
__device__ int   g_cnt[NN];
__device__ int   g_colidx[EE];
__device__ float g_stats[2 * HH];
__device__ float g_mv[2 * HH];

// ---------------- PTX helpers (sm_80-level, sm_100-safe) ----------------
__device__ __forceinline__ uint32_t smem_u32(const void* p) {
    uint32_t a;
    asm("{ .reg .u64 t; cvta.to.shared.u64 t, %1; cvt.u32.u64 %0, t; }" : "=r"(a) : "l"(p));
    return a;
}
__device__ __forceinline__ uint32_t sw64(uint32_t b) { return b ^ ((b >> 3) & 0x30); }

__device__ __forceinline__ void cpa16(uint32_t dst, const void* src, bool pred) {
    int sz = pred ? 16 : 0;
    asm volatile("cp.async.cg.shared.global [%0], [%1], 16, %2;"
                 :: "r"(dst), "l"(src), "r"(sz) : "memory");
}
__device__ __forceinline__ void cpa_commit() {
    asm volatile("cp.async.commit_group;" ::: "memory");
}
template <int N>
__device__ __forceinline__ void cpa_wait() {
    asm volatile("cp.async.wait_group %0;" :: "n"(N) : "memory");
}
__device__ __forceinline__ void ldmx4(uint32_t* r, uint32_t addr) {
    asm volatile("ldmatrix.sync.aligned.m8n8.x4.shared.b16 {%0,%1,%2,%3}, [%4];"
                 : "=r"(r[0]), "=r"(r[1]), "=r"(r[2]), "=r"(r[3]) : "r"(addr));
}
__device__ __forceinline__ void mma16816(float* c, const uint32_t* a, const uint32_t* b) {
    asm volatile(
        "mma.sync.aligned.m16n8k16.row.col.f32.f16.f16.f32 "
        "{%0,%1,%2,%3},{%4,%5,%6,%7},{%8,%9},{%0,%1,%2,%3};"
        : "+f"(c[0]), "+f"(c[1]), "+f"(c[2]), "+f"(c[3])
        : "r"(a[0]), "r"(a[1]), "r"(a[2]), "r"(a[3]), "r"(b[0]), "r"(b[1]));
}

// ---------------- CSR build ----------------
__global__ void zero_cnt_k() {
    int i = blockIdx.x * blockDim.x + threadIdx.x;
    if (i < NN) g_cnt[i] = 0;
}
__global__ void count_deg_k(const int* __restrict__ ei) {
    int e = blockIdx.x * blockDim.x + threadIdx.x;
    if (e < EE) atomicAdd(&g_cnt[__ldg(ei + EE + e)], 1);
}
__global__ void scan_k() {
    __shared__ int sm[1024];
    int t = threadIdx.x;
    const int CH = (NN + 1023) / 1024;
    int base = t * CH;
    int s = 0;
    for (int i = 0; i < CH; i++) {
        int idx = base + i;
        if (idx < NN) s += g_cnt[idx];
    }
    sm[t] = s;
    __syncthreads();
    for (int off = 1; off < 1024; off <<= 1) {
        int v = 0;
        if (t >= off) v = sm[t - off];
        __syncthreads();
        if (t >= off) sm[t] += v;
        __syncthreads();
    }
    int run = (t == 0) ? 0 : sm[t - 1];
    for (int i = 0; i < CH; i++) {
        int idx = base + i;
        if (idx < NN) {
            g_rowptr[idx] = run;
            run += g_cnt[idx];
        }
    }
    if (t == 1023) g_rowptr[NN] = run;
}
__global__ void fill_col_k(const int* __restrict__ ei) {
    int e = blockIdx.x * blockDim.x + threadIdx.x;
    if (e < EE) {
        int dst = __ldg(ei + EE + e);
        int pos = g_rowptr[dst] + atomicAdd(&g_cnt[dst], 1);
        g_colidx[pos] = __ldg(ei + e);
    }
}

// ---------------- fused aggregation ----------------
__device__ __forceinline__ void store_h4(int node, int c, const float4& acc) {
    __half2 h0 = __floats2half2_rn(acc.x, acc.y);
    __half2 h1 = __floats2half2_rn(acc.z, acc.w);
    uint2 v;
    v.x = *(uint32_t*)&h0;
    v.y = *(uint32_t*)&h1;
    *(uint2*)(g_Sh + (size_t)node * KK + c) = v;
}

// layer 0: S = emb[xi[node]] + sum emb[xi[src]]
__global__ void agg_emb_k(const int* __restrict__ xi, const float* __restrict__ emb) {
    __shared__ int snb[128];
    int node = blockIdx.x;
    int tid = threadIdx.x;
    int c = tid << 2;
    float4 acc = *(const float4*)(emb + (size_t)__ldg(xi + node) * KK + c);
    int ps = g_rowptr[node], pe = g_rowptr[node + 1];
    for (int base = ps; base < pe; base += 128) {
        int n = min(128, pe - base);
        __syncthreads();
        if (tid < n) snb[tid] = __ldg(xi + __ldg(g_colidx + base + tid));
        __syncthreads();
        for (int j = 0; j < n; j++) {
            const float4 v = *(const float4*)(emb + (size_t)snb[j] * KK + c);
            acc.x += v.x; acc.y += v.y; acc.z += v.z; acc.w += v.w;
        }
    }
    store_h4(node, c, acc);
}

// layers 1,2: x = relu(bn(Y)) on the fly; S = x[node] + sum x[src]
__global__ void agg_bn_k() {
    __shared__ int snb[128];
    int node = blockIdx.x;
    int tid = threadIdx.x;
    int c = tid << 2;
    float4 sc = *(const float4*)(g_mv + c);
    float4 sh = *(const float4*)(g_mv + HH + c);
    const float4* Y4 = (const float4*)g_Y;
    float4 y = Y4[((size_t)node * KK + c) >> 2];
    float4 acc;
    acc.x = fmaxf(fmaf(y.x, sc.x, sh.x), 0.f);
    acc.y = fmaxf(fmaf(y.y, sc.y, sh.y), 0.f);
    acc.z = fmaxf(fmaf(y.z, sc.z, sh.z), 0.f);
    acc.w = fmaxf(fmaf(y.w, sc.w, sh.w), 0.f);
    int ps = g_rowptr[node], pe = g_rowptr[node + 1];
    for (int base = ps; base < pe; base += 128) {
        int n = min(128, pe - base);
        __syncthreads();
        if (tid < n) snb[tid] = __ldg(g_colidx + base + tid);
        __syncthreads();
        for (int j = 0; j < n; j++) {
            float4 v = Y4[((size_t)snb[j] * KK + c) >> 2];
            acc.x += fmaxf(fmaf(v.x, sc.x, sh.x), 0.f);
            acc.y += fmaxf(fmaf(v.y, sc.y, sh.y), 0.f);
            acc.z += fmaxf(fmaf(v.z, sc.z, sh.z), 0.f);
            acc.w += fmaxf(fmaf(v.w, sc.w, sh.w), 0.f);
        }
    }
    store_h4(node, c, acc);
}

// ---------------- BN stats ----------------
__global__ void zero_stats_k() {
    int i = threadIdx.x;
    g_stats[i] = 0.f;
    g_stats[HH + i] = 0.f;
}
#define SROWS 250
__global__ void stats_k() {
    int c = threadIdx.x;
    int r0 = blockIdx.x * SROWS;
    int r1 = min(r0 + SROWS, NN);
    float s0 = 0.f, q0 = 0.f, s1 = 0.f, q1 = 0.f;
    for (int r = r0; r < r1; r++) {
        float v0 = g_Y[(size_t)r * HH + c];
        float v1 = g_Y[(size_t)r * HH + c + 256];
        s0 += v0; q0 += v0 * v0;
        s1 += v1; q1 += v1 * v1;
    }
    atomicAdd(&g_stats[c], s0);
    atomicAdd(&g_stats[HH + c], q0);
    atomicAdd(&g_stats[c + 256], s1);
    atomicAdd(&g_stats[HH + c + 256], q1);
}
__global__ void finalize_k(const float* __restrict__ gam, const float* __restrict__ bet) {
    int c = threadIdx.x;
    float mu = g_stats[c] * (1.f / NN);
    float var = g_stats[HH + c] * (1.f / NN) - mu * mu;
    float sc = rsqrtf(var + BN_EPS) * gam[c];
    g_mv[c] = sc;
    g_mv[HH + c] = bet[c] - mu * sc;
}

// ---------------- weight transpose + fp16 split ----------------
__global__ void wsplit_k(const float* __restrict__ w, __half* __restrict__ th,
                         __half* __restrict__ tl, int Ndim) {
    __shared__ float t[32][33];
    int bx = blockIdx.x * 32;  // k
    int by = blockIdx.y * 32;  // n
    int x = threadIdx.x, y = threadIdx.y;
#pragma unroll
    for (int i = 0; i < 32; i += 8)
        t[y + i][x] = w[(size_t)(bx + y + i) * Ndim + by + x];
    __syncthreads();
#pragma unroll
    for (int i = 0; i < 32; i += 8) {
        float v = t[x][y + i];
        __half h = __float2half_rn(v);
        float lo = v - __half2float(h);
        th[(size_t)(by + y + i) * KK + bx + x] = h;
        tl[(size_t)(by + y + i) * KK + bx + x] = __float2half_rn(lo);
    }
}

// ---------------- mma.sync GEMM (2-stage x 24KB: A + Wh + Wl per chunk) ----------------
__device__ __forceinline__ void load_chunk(
    uint32_t stg,
    const __half* __restrict__ A, const __half* __restrict__ Wh,
    const __half* __restrict__ Wl,
    int mBase, int M, int nBase, int kk, int tid)
{
#pragma unroll
    for (int i = 0; i < 2; i++) {
        int idx = i * 256 + tid;
        int row = idx >> 2, cu = idx & 3;
        int grow = mBase + row;
        const char* src = (const char*)(A + (size_t)grow * KK + kk) + cu * 16;
        cpa16(stg + sw64(row * 64 + cu * 16), src, grow < M);
    }
#pragma unroll
    for (int i = 0; i < 2; i++) {
        int idx = i * 256 + tid;
        int row = idx >> 2, cu = idx & 3;
        const char* src = (const char*)(Wh + (size_t)(nBase + row) * KK + kk) + cu * 16;
        cpa16(stg + 8192 + sw64(row * 64 + cu * 16), src, true);
    }
#pragma unroll
    for (int i = 0; i < 2; i++) {
        int idx = i * 256 + tid;
        int row = idx >> 2, cu = idx & 3;
        const char* src = (const char*)(Wl + (size_t)(nBase + row) * KK + kk) + cu * 16;
        cpa16(stg + 16384 + sw64(row * 64 + cu * 16), src, true);
    }
}

// MODE 0: bias+relu -> fp16 H ; MODE 1: bias -> fp32 Y ; MODE 2: bias -> fp32 out
template <int MODE>
__global__ void __launch_bounds__(256) gemm_mma(
    const __half* __restrict__ Ah,
    const __half* __restrict__ Wh, const __half* __restrict__ Wl,
    const float* __restrict__ bias,
    float* __restrict__ Cf, __half* __restrict__ Ch,
    int M, int Ncols)
{
    __shared__ __align__(1024) uint8_t smem[2 * STG];  // 48KB static
    uint32_t sbase = smem_u32(smem);

    const int tid = threadIdx.x, lane = tid & 31, wid = tid >> 5;
    const int wm = wid >> 1, wn = wid & 1;
    const int mBase = blockIdx.y * BM;
    const int nBase = blockIdx.x * BNT;

    float acc[2][8][4];
#pragma unroll
    for (int a = 0; a < 2; a++)
#pragma unroll
        for (int b = 0; b < 8; b++)
#pragma unroll
            for (int c = 0; c < 4; c++) acc[a][b][c] = 0.f;

    load_chunk(sbase, Ah, Wh, Wl, mBase, M, nBase, 0, tid);
    cpa_commit();
    load_chunk(sbase + STG, Ah, Wh, Wl, mBase, M, nBase, 32, tid);
    cpa_commit();

    for (int kc = 0; kc < NCHK; kc++) {
        if (kc + 1 < NCHK) cpa_wait<1>();
        else               cpa_wait<0>();
        __syncthreads();

        uint32_t stg = sbase + (kc & 1) * STG;
#pragma unroll
        for (int k16 = 0; k16 < 2; k16++) {
            uint32_t aF[2][4];
#pragma unroll
            for (int fm = 0; fm < 2; fm++) {
                int row = wm * 32 + fm * 16 + (lane & 15);
                int cu = 2 * k16 + (lane >> 4);
                ldmx4(aF[fm], stg + sw64(row * 64 + cu * 16));
            }
#pragma unroll
            for (int seg = 0; seg < 2; seg++) {
                uint32_t bT = stg + 8192 + seg * 8192;
                uint32_t bF[4][4];
#pragma unroll
                for (int g = 0; g < 4; g++) {
                    int half = (lane >> 3) & 1;
                    int sel = lane >> 4;
                    int row = wn * 64 + g * 16 + sel * 8 + (lane & 7);
                    int cu = 2 * k16 + half;
                    ldmx4(bF[g], bT + sw64(row * 64 + cu * 16));
                }
#pragma unroll
                for (int fm = 0; fm < 2; fm++)
#pragma unroll
                    for (int fn = 0; fn < 8; fn++)
                        mma16816(acc[fm][fn], aF[fm], &bF[fn >> 1][(fn & 1) * 2]);
            }
        }
        __syncthreads();
        if (kc + 2 < NCHK) {
            load_chunk(sbase + (kc & 1) * STG, Ah, Wh, Wl,
                       mBase, M, nBase, (kc + 2) * 32, tid);
            cpa_commit();
        }
    }

    // ---- epilogue ----
#pragma unroll
    for (int fn = 0; fn < 8; fn++) {
        int col = nBase + wn * 64 + fn * 8 + (lane & 3) * 2;
        float bv0 = __ldg(bias + col);
        float bv1 = __ldg(bias + col + 1);
#pragma unroll
        for (int fm = 0; fm < 2; fm++) {
            int rowb = mBase + wm * 32 + fm * 16 + (lane >> 2);
            float* a = acc[fm][fn];
#pragma unroll
            for (int h = 0; h < 2; h++) {
                int r = rowb + 8 * h;
                if (r < M) {
                    float v0 = a[2 * h] + bv0, v1 = a[2 * h + 1] + bv1;
                    if (MODE == 0) {
                        v0 = fmaxf(v0, 0.f);
                        v1 = fmaxf(v1, 0.f);
                        __half2 hp = __floats2half2_rn(v0, v1);
                        *(__half2*)(Ch + (size_t)r * Ncols + col) = hp;
                    } else {
                        float2 o; o.x = v0; o.y = v1;
                        *(float2*)(Cf + (size_t)r * Ncols + col) = o;
                    }
                }
            }
        }
    }
}

// ---------------- driver ----------------
extern "C" void kernel_launch(void* const* d_in, const int* in_sizes, int n_in,
                              void* d_out, int out_size) {
    const int*   xi  = (const int*)d_in[0];
    const int*   ei  = (const int*)d_in[1];
    const float* emb = (const float*)d_in[2];
    const float* w1[3] = {(const float*)d_in[3], (const float*)d_in[9],  (const float*)d_in[15]};
    const float* b1[3] = {(const float*)d_in[4], (const float*)d_in[10], (const float*)d_in[16]};
    const float* w2[3] = {(const float*)d_in[5], (const float*)d_in[11], (const float*)d_in[17]};
    const float* b2[3] = {(const float*)d_in[6], (const float*)d_in[12], (const float*)d_in[18]};
    const float* gam[2] = {(const float*)d_in[7], (const float*)d_in[13]};
    const float* bet[2] = {(const float*)d_in[8], (const float*)d_in[14]};

    __half *pSh, *pHh, *pWh, *pWl, *pVh, *pVl;
    float *pY;
    cudaGetSymbolAddress((void**)&pSh, g_Sh);
    cudaGetSymbolAddress((void**)&pHh, g_Hh);
    cudaGetSymbolAddress((void**)&pWh, g_Wh);
    cudaGetSymbolAddress((void**)&pWl, g_Wl);
    cudaGetSymbolAddress((void**)&pVh, g_Vh);
    cudaGetSymbolAddress((void**)&pVl, g_Vl);
    cudaGetSymbolAddress((void**)&pY, g_Y);

    dim3 tb(32, 8);
    dim3 gw512(KK / 32, 512 / 32);
    dim3 gw256(KK / 32, 256 / 32);

    // weight splits (independent — front of graph)
    for (int l = 0; l < 3; ++l) {
        wsplit_k<<<gw512, tb>>>(w1[l], pWh + (size_t)l * KK * HH, pWl + (size_t)l * KK * HH, 512);
        if (l < 2)
            wsplit_k<<<gw512, tb>>>(w2[l], pVh + (size_t)l * KK * HH, pVl + (size_t)l * KK * HH, 512);
        else
            wsplit_k<<<gw256, tb>>>(w2[2], pVh + (size_t)2 * KK * HH, pVl + (size_t)2 * KK * HH, 256);
    }

    // CSR build
    zero_cnt_k<<<(NN + 255) / 256, 256>>>();
    count_deg_k<<<(EE + 255) / 256, 256>>>(ei);
    scan_k<<<1, 1024>>>();
    zero_cnt_k<<<(NN + 255) / 256, 256>>>();
    fill_col_k<<<(EE + 255) / 256, 256>>>(ei);

    dim3 gg512(512 / BNT, (NN + BM - 1) / BM);
    dim3 gg256(256 / BNT, (NN + BM - 1) / BM);

    for (int l = 0; l < 3; ++l) {
        if (l == 0) agg_emb_k<<<NN, 128>>>(xi, emb);
        else        agg_bn_k<<<NN, 128>>>();

        gemm_mma<0><<<gg512, 256>>>(pSh,
            pWh + (size_t)l * KK * HH, pWl + (size_t)l * KK * HH, b1[l],
            nullptr, pHh, NN, 512);

        if (l < 2) {
            gemm_mma<1><<<gg512, 256>>>(pHh,
                pVh + (size_t)l * KK * HH, pVl + (size_t)l * KK * HH, b2[l],
                pY, nullptr, NN, 512);
            zero_stats_k<<<1, HH>>>();
            stats_k<<<(NN + SROWS - 1) / SROWS, 256>>>();
            finalize_k<<<1, HH>>>(gam[l], bet[l]);
        } else {
            gemm_mma<2><<<gg256, 256>>>(pHh,
                pVh + (size_t)2 * KK * HH, pVl + (size_t)2 * KK * HH, b2[2],
                (float*)d_out, nullptr, NN, 256);
        }
    }
}

// round 10
// speedup vs baseline: 4.0405x; 1.3056x over previous
#include <cuda_runtime.h>
#include <cuda_fp16.h>
#include <stdint.h>

#define NN 50000
#define EE 400000
#define HH 512
#define OO 256
#define KK 512
#define BN_EPS 1e-5f

#define BM 128
#define BNT 128          // N tile
#define NCH 16           // 16 chunks of K=32, single fp16 term

// ---------------- scratch (device globals) ----------------
__device__ __align__(256) float g_Y[(size_t)NN * HH];
__device__ __align__(256) __half g_Sh[(size_t)NN * KK];          // fp16(S)
__device__ __align__(256) __half g_Hh[(size_t)NN * HH];          // fp16(relu(gemm1))
__device__ __align__(256) __half g_Wh[3][KK * HH];               // w1 fp16 [N][K]
__device__ __align__(256) __half g_Vh[3][KK * HH];               // w2 fp16 [N][K]
__device__ int   g_rowptr[NN + 1];
__device__ int   g_cnt[NN];
__device__ int   g_colidx[EE];
__device__ float g_stats[2 * HH];
__device__ float g_mv[2 * HH];

// ---------------- PTX helpers (sm_80-level, sm_100-safe) ----------------
__device__ __forceinline__ uint32_t smem_u32(const void* p) {
    uint32_t a;
    asm("{ .reg .u64 t; cvta.to.shared.u64 t, %1; cvt.u32.u64 %0, t; }" : "=r"(a) : "l"(p));
    return a;
}
__device__ __forceinline__ uint32_t sw64(uint32_t b) { return b ^ ((b >> 3) & 0x30); }

__device__ __forceinline__ void cpa16(uint32_t dst, const void* src, bool pred) {
    int sz = pred ? 16 : 0;
    asm volatile("cp.async.cg.shared.global [%0], [%1], 16, %2;"
                 :: "r"(dst), "l"(src), "r"(sz) : "memory");
}
__device__ __forceinline__ void cpa_commit() {
    asm volatile("cp.async.commit_group;" ::: "memory");
}
template <int N>
__device__ __forceinline__ void cpa_wait() {
    asm volatile("cp.async.wait_group %0;" :: "n"(N) : "memory");
}
__device__ __forceinline__ void ldmx4(uint32_t* r, uint32_t addr) {
    asm volatile("ldmatrix.sync.aligned.m8n8.x4.shared.b16 {%0,%1,%2,%3}, [%4];"
                 : "=r"(r[0]), "=r"(r[1]), "=r"(r[2]), "=r"(r[3]) : "r"(addr));
}
__device__ __forceinline__ void mma16816(float* c, const uint32_t* a, const uint32_t* b) {
    asm volatile(
        "mma.sync.aligned.m16n8k16.row.col.f32.f16.f16.f32 "
        "{%0,%1,%2,%3},{%4,%5,%6,%7},{%8,%9},{%0,%1,%2,%3};"
        : "+f"(c[0]), "+f"(c[1]), "+f"(c[2]), "+f"(c[3])
        : "r"(a[0]), "r"(a[1]), "r"(a[2]), "r"(a[3]), "r"(b[0]), "r"(b[1]));
}

// ---------------- CSR build ----------------
__global__ void zero_cnt_k() {
    int i = blockIdx.x * blockDim.x + threadIdx.x;
    if (i < NN) g_cnt[i] = 0;
}
__global__ void count_deg_k(const int* __restrict__ ei) {
    int e = blockIdx.x * blockDim.x + threadIdx.x;
    if (e < EE) atomicAdd(&g_cnt[__ldg(ei + EE + e)], 1);
}
__global__ void scan_k() {
    __shared__ int sm[1024];
    int t = threadIdx.x;
    const int CH = (NN + 1023) / 1024;
    int base = t * CH;
    int s = 0;
    for (int i = 0; i < CH; i++) {
        int idx = base + i;
        if (idx < NN) s += g_cnt[idx];
    }
    sm[t] = s;
    __syncthreads();
    for (int off = 1; off < 1024; off <<= 1) {
        int v = 0;
        if (t >= off) v = sm[t - off];
        __syncthreads();
        if (t >= off) sm[t] += v;
        __syncthreads();
    }
    int run = (t == 0) ? 0 : sm[t - 1];
    for (int i = 0; i < CH; i++) {
        int idx = base + i;
        if (idx < NN) {
            g_rowptr[idx] = run;
            run += g_cnt[idx];
        }
    }
    if (t == 1023) g_rowptr[NN] = run;
}
__global__ void fill_col_k(const int* __restrict__ ei) {
    int e = blockIdx.x * blockDim.x + threadIdx.x;
    if (e < EE) {
        int dst = __ldg(ei + EE + e);
        int pos = g_rowptr[dst] + atomicAdd(&g_cnt[dst], 1);
        g_colidx[pos] = __ldg(ei + e);
    }
}

// ---------------- fused aggregation ----------------
__device__ __forceinline__ void store_h4(int node, int c, const float4& acc) {
    __half2 h0 = __floats2half2_rn(acc.x, acc.y);
    __half2 h1 = __floats2half2_rn(acc.z, acc.w);
    uint2 v;
    v.x = *(uint32_t*)&h0;
    v.y = *(uint32_t*)&h1;
    *(uint2*)(g_Sh + (size_t)node * KK + c) = v;
}

// layer 0: S = emb[xi[node]] + sum emb[xi[src]]
__global__ void agg_emb_k(const int* __restrict__ xi, const float* __restrict__ emb) {
    __shared__ int snb[128];
    int node = blockIdx.x;
    int tid = threadIdx.x;
    int c = tid << 2;
    float4 acc = *(const float4*)(emb + (size_t)__ldg(xi + node) * KK + c);
    int ps = g_rowptr[node], pe = g_rowptr[node + 1];
    for (int base = ps; base < pe; base += 128) {
        int n = min(128, pe - base);
        __syncthreads();
        if (tid < n) snb[tid] = __ldg(xi + __ldg(g_colidx + base + tid));
        __syncthreads();
        for (int j = 0; j < n; j++) {
            const float4 v = *(const float4*)(emb + (size_t)snb[j] * KK + c);
            acc.x += v.x; acc.y += v.y; acc.z += v.z; acc.w += v.w;
        }
    }
    store_h4(node, c, acc);
}

// layers 1,2: x = relu(bn(Y)) on the fly; S = x[node] + sum x[src]
__global__ void agg_bn_k() {
    __shared__ int snb[128];
    int node = blockIdx.x;
    int tid = threadIdx.x;
    int c = tid << 2;
    float4 sc = *(const float4*)(g_mv + c);
    float4 sh = *(const float4*)(g_mv + HH + c);
    const float4* Y4 = (const float4*)g_Y;
    float4 y = Y4[((size_t)node * KK + c) >> 2];
    float4 acc;
    acc.x = fmaxf(fmaf(y.x, sc.x, sh.x), 0.f);
    acc.y = fmaxf(fmaf(y.y, sc.y, sh.y), 0.f);
    acc.z = fmaxf(fmaf(y.z, sc.z, sh.z), 0.f);
    acc.w = fmaxf(fmaf(y.w, sc.w, sh.w), 0.f);
    int ps = g_rowptr[node], pe = g_rowptr[node + 1];
    for (int base = ps; base < pe; base += 128) {
        int n = min(128, pe - base);
        __syncthreads();
        if (tid < n) snb[tid] = __ldg(g_colidx + base + tid);
        __syncthreads();
        for (int j = 0; j < n; j++) {
            float4 v = Y4[((size_t)snb[j] * KK + c) >> 2];
            acc.x += fmaxf(fmaf(v.x, sc.x, sh.x), 0.f);
            acc.y += fmaxf(fmaf(v.y, sc.y, sh.y), 0.f);
            acc.z += fmaxf(fmaf(v.z, sc.z, sh.z), 0.f);
            acc.w += fmaxf(fmaf(v.w, sc.w, sh.w), 0.f);
        }
    }
    store_h4(node, c, acc);
}

// ---------------- BN stats ----------------
__global__ void zero_stats_k() {
    int i = threadIdx.x;
    g_stats[i] = 0.f;
    g_stats[HH + i] = 0.f;
}
#define SROWS 250
__global__ void stats_k() {
    int c = threadIdx.x;
    int r0 = blockIdx.x * SROWS;
    int r1 = min(r0 + SROWS, NN);
    float s0 = 0.f, q0 = 0.f, s1 = 0.f, q1 = 0.f;
    for (int r = r0; r < r1; r++) {
        float v0 = g_Y[(size_t)r * HH + c];
        float v1 = g_Y[(size_t)r * HH + c + 256];
        s0 += v0; q0 += v0 * v0;
        s1 += v1; q1 += v1 * v1;
    }
    atomicAdd(&g_stats[c], s0);
    atomicAdd(&g_stats[HH + c], q0);
    atomicAdd(&g_stats[c + 256], s1);
    atomicAdd(&g_stats[HH + c + 256], q1);
}
__global__ void finalize_k(const float* __restrict__ gam, const float* __restrict__ bet) {
    int c = threadIdx.x;
    float mu = g_stats[c] * (1.f / NN);
    float var = g_stats[HH + c] * (1.f / NN) - mu * mu;
    float sc = rsqrtf(var + BN_EPS) * gam[c];
    g_mv[c] = sc;
    g_mv[HH + c] = bet[c] - mu * sc;
}

// ---------------- weight transpose + fp16 convert ----------------
__global__ void wsplit_k(const float* __restrict__ w, __half* __restrict__ th, int Ndim) {
    __shared__ float t[32][33];
    int bx = blockIdx.x * 32;  // k
    int by = blockIdx.y * 32;  // n
    int x = threadIdx.x, y = threadIdx.y;
#pragma unroll
    for (int i = 0; i < 32; i += 8)
        t[y + i][x] = w[(size_t)(bx + y + i) * Ndim + by + x];
    __syncthreads();
#pragma unroll
    for (int i = 0; i < 32; i += 8)
        th[(size_t)(by + y + i) * KK + bx + x] = __float2half_rn(t[x][y + i]);
}

// ---------------- mma.sync GEMM (BK=32, static 48KB smem, 3-stage) ----------------
__device__ __forceinline__ void load_tiles(
    uint32_t sa, uint32_t sb,
    const __half* __restrict__ A, const __half* __restrict__ W,
    int mBase, int M, int nBase, int kk, int tid)
{
#pragma unroll
    for (int i = 0; i < 2; i++) {
        int idx = i * 256 + tid;
        int row = idx >> 2, cu = idx & 3;
        int grow = mBase + row;
        const char* src = (const char*)(A + (size_t)grow * KK + kk) + cu * 16;
        cpa16(sa + sw64(row * 64 + cu * 16), src, grow < M);
    }
#pragma unroll
    for (int i = 0; i < 2; i++) {
        int idx = i * 256 + tid;
        int row = idx >> 2, cu = idx & 3;
        const char* src = (const char*)(W + (size_t)(nBase + row) * KK + kk) + cu * 16;
        cpa16(sb + sw64(row * 64 + cu * 16), src, true);
    }
}

// MODE 0: bias+relu -> fp16 H ; MODE 1: bias -> fp32 Y ; MODE 2: bias -> fp32 out
template <int MODE>
__global__ void __launch_bounds__(256) gemm_mma(
    const __half* __restrict__ Ah, const __half* __restrict__ Wt,
    const float* __restrict__ bias,
    float* __restrict__ Cf, __half* __restrict__ Ch,
    int M, int Ncols)
{
    __shared__ __align__(1024) uint8_t smem[3 * 16384];  // 3 stages x (A 8K + B 8K)
    uint32_t sbase = smem_u32(smem);

    const int tid = threadIdx.x, lane = tid & 31, wid = tid >> 5;
    const int wm = wid >> 1, wn = wid & 1;
    const int mBase = blockIdx.y * BM;
    const int nBase = blockIdx.x * BNT;

    float acc[2][8][4];
#pragma unroll
    for (int a = 0; a < 2; a++)
#pragma unroll
        for (int b = 0; b < 8; b++)
#pragma unroll
            for (int c = 0; c < 4; c++) acc[a][b][c] = 0.f;

    load_tiles(sbase, sbase + 8192, Ah, Wt, mBase, M, nBase, 0, tid);
    cpa_commit();
    load_tiles(sbase + 16384, sbase + 16384 + 8192, Ah, Wt, mBase, M, nBase, 32, tid);
    cpa_commit();

    for (int kc = 0; kc < NCH; kc++) {
        int buf = kc % 3;
        if (kc + 2 < NCH) {
            int nb = (kc + 2) % 3;
            load_tiles(sbase + nb * 16384, sbase + nb * 16384 + 8192,
                       Ah, Wt, mBase, M, nBase, (kc + 2) * 32, tid);
            cpa_commit();
            cpa_wait<2>();
        } else {
            cpa_wait<0>();
        }
        __syncthreads();

        uint32_t aT = sbase + buf * 16384;
        uint32_t bT = aT + 8192;
#pragma unroll
        for (int k16 = 0; k16 < 2; k16++) {
            uint32_t aF[2][4];
#pragma unroll
            for (int fm = 0; fm < 2; fm++) {
                int row = wm * 32 + fm * 16 + (lane & 15);
                int cu = 2 * k16 + (lane >> 4);
                ldmx4(aF[fm], aT + sw64(row * 64 + cu * 16));
            }
            uint32_t bF[4][4];
#pragma unroll
            for (int g = 0; g < 4; g++) {
                int half = (lane >> 3) & 1;
                int sel = lane >> 4;
                int row = wn * 64 + g * 16 + sel * 8 + (lane & 7);
                int cu = 2 * k16 + half;
                ldmx4(bF[g], bT + sw64(row * 64 + cu * 16));
            }
#pragma unroll
            for (int fm = 0; fm < 2; fm++)
#pragma unroll
                for (int fn = 0; fn < 8; fn++)
                    mma16816(acc[fm][fn], aF[fm], &bF[fn >> 1][(fn & 1) * 2]);
        }
        __syncthreads();
    }

    // ---- epilogue ----
#pragma unroll
    for (int fn = 0; fn < 8; fn++) {
        int col = nBase + wn * 64 + fn * 8 + (lane & 3) * 2;
        float bv0 = __ldg(bias + col);
        float bv1 = __ldg(bias + col + 1);
#pragma unroll
        for (int fm = 0; fm < 2; fm++) {
            int rowb = mBase + wm * 32 + fm * 16 + (lane >> 2);
            float* a = acc[fm][fn];
#pragma unroll
            for (int h = 0; h < 2; h++) {
                int r = rowb + 8 * h;
                if (r < M) {
                    float v0 = a[2 * h] + bv0, v1 = a[2 * h + 1] + bv1;
                    if (MODE == 0) {
                        v0 = fmaxf(v0, 0.f);
                        v1 = fmaxf(v1, 0.f);
                        __half2 hp = __floats2half2_rn(v0, v1);
                        *(__half2*)(Ch + (size_t)r * Ncols + col) = hp;
                    } else {
                        float2 o; o.x = v0; o.y = v1;
                        *(float2*)(Cf + (size_t)r * Ncols + col) = o;
                    }
                }
            }
        }
    }
}

// ---------------- driver ----------------
extern "C" void kernel_launch(void* const* d_in, const int* in_sizes, int n_in,
                              void* d_out, int out_size) {
    const int*   xi  = (const int*)d_in[0];
    const int*   ei  = (const int*)d_in[1];
    const float* emb = (const float*)d_in[2];
    const float* w1[3] = {(const float*)d_in[3], (const float*)d_in[9],  (const float*)d_in[15]};
    const float* b1[3] = {(const float*)d_in[4], (const float*)d_in[10], (const float*)d_in[16]};
    const float* w2[3] = {(const float*)d_in[5], (const float*)d_in[11], (const float*)d_in[17]};
    const float* b2[3] = {(const float*)d_in[6], (const float*)d_in[12], (const float*)d_in[18]};
    const float* gam[2] = {(const float*)d_in[7], (const float*)d_in[13]};
    const float* bet[2] = {(const float*)d_in[8], (const float*)d_in[14]};

    __half *pSh, *pHh, *pWh, *pVh;
    float *pY;
    cudaGetSymbolAddress((void**)&pSh, g_Sh);
    cudaGetSymbolAddress((void**)&pHh, g_Hh);
    cudaGetSymbolAddress((void**)&pWh, g_Wh);
    cudaGetSymbolAddress((void**)&pVh, g_Vh);
    cudaGetSymbolAddress((void**)&pY, g_Y);

    dim3 tb(32, 8);
    dim3 gw512(KK / 32, 512 / 32);
    dim3 gw256(KK / 32, 256 / 32);

    // weight transposes (independent — front of graph)
    for (int l = 0; l < 3; ++l) {
        wsplit_k<<<gw512, tb>>>(w1[l], pWh + (size_t)l * KK * HH, 512);
        if (l < 2)
            wsplit_k<<<gw512, tb>>>(w2[l], pVh + (size_t)l * KK * HH, 512);
        else
            wsplit_k<<<gw256, tb>>>(w2[2], pVh + (size_t)2 * KK * HH, 256);
    }

    // CSR build
    zero_cnt_k<<<(NN + 255) / 256, 256>>>();
    count_deg_k<<<(EE + 255) / 256, 256>>>(ei);
    scan_k<<<1, 1024>>>();
    zero_cnt_k<<<(NN + 255) / 256, 256>>>();
    fill_col_k<<<(EE + 255) / 256, 256>>>(ei);

    dim3 gg512(512 / BNT, (NN + BM - 1) / BM);
    dim3 gg256(256 / BNT, (NN + BM - 1) / BM);

    for (int l = 0; l < 3; ++l) {
        if (l == 0) agg_emb_k<<<NN, 128>>>(xi, emb);
        else        agg_bn_k<<<NN, 128>>>();

        gemm_mma<0><<<gg512, 256>>>(pSh,
            pWh + (size_t)l * KK * HH, b1[l], nullptr, pHh, NN, 512);

        if (l < 2) {
            gemm_mma<1><<<gg512, 256>>>(pHh,
                pVh + (size_t)l * KK * HH, b2[l], pY, nullptr, NN, 512);
            zero_stats_k<<<1, HH>>>();
            stats_k<<<(NN + SROWS - 1) / SROWS, 256>>>();
            finalize_k<<<1, HH>>>(gam[l], bet[l]);
        } else {
            gemm_mma<2><<<gg256, 256>>>(pHh,
                pVh + (size_t)2 * KK * HH, b2[2], (float*)d_out, nullptr, NN, 256);
        }
    }
}

// round 11
// speedup vs baseline: 4.6047x; 1.1396x over previous
#include <cuda_runtime.h>
#include <cuda_fp16.h>
#include <stdint.h>

#define NN 50000
#define EE 400000
#define HH 512
#define OO 256
#define KK 512
#define BN_EPS 1e-5f

#define BM 128
#define BNT 128          // N tile
#define NCH 16           // 16 chunks of K=32, single fp16 term

// ---------------- scratch (device globals) ----------------
__device__ __align__(256) __half g_Y[(size_t)NN * HH];           // fp16 pre-BN gemm2 out
__device__ __align__(256) __half g_Eh[(size_t)NN * KK];          // fp16(emb)
__device__ __align__(256) __half g_Sh[(size_t)NN * KK];          // fp16(S)
__device__ __align__(256) __half g_Hh[(size_t)NN * HH];          // fp16(relu(gemm1))
__device__ __align__(256) __half g_Wh[3][KK * HH];               // w1 fp16 [N][K]
__device__ __align__(256) __half g_Vh[3][KK * HH];               // w2 fp16 [N][K]
__device__ int   g_rowptr[NN + 1];
__device__ int   g_cnt[NN];
__device__ int   g_colidx[EE];
__device__ float g_stats[2 * HH];
__device__ float g_mv[2 * HH];

// ---------------- PTX helpers (sm_80-level, sm_100-safe) ----------------
__device__ __forceinline__ uint32_t smem_u32(const void* p) {
    uint32_t a;
    asm("{ .reg .u64 t; cvta.to.shared.u64 t, %1; cvt.u32.u64 %0, t; }" : "=r"(a) : "l"(p));
    return a;
}
__device__ __forceinline__ uint32_t sw64(uint32_t b) { return b ^ ((b >> 3) & 0x30); }

__device__ __forceinline__ void cpa16(uint32_t dst, const void* src, bool pred) {
    int sz = pred ? 16 : 0;
    asm volatile("cp.async.cg.shared.global [%0], [%1], 16, %2;"
                 :: "r"(dst), "l"(src), "r"(sz) : "memory");
}
__device__ __forceinline__ void cpa_commit() {
    asm volatile("cp.async.commit_group;" ::: "memory");
}
template <int N>
__device__ __forceinline__ void cpa_wait() {
    asm volatile("cp.async.wait_group %0;" :: "n"(N) : "memory");
}
__device__ __forceinline__ void ldmx4(uint32_t* r, uint32_t addr) {
    asm volatile("ldmatrix.sync.aligned.m8n8.x4.shared.b16 {%0,%1,%2,%3}, [%4];"
                 : "=r"(r[0]), "=r"(r[1]), "=r"(r[2]), "=r"(r[3]) : "r"(addr));
}
__device__ __forceinline__ void mma16816(float* c, const uint32_t* a, const uint32_t* b) {
    asm volatile(
        "mma.sync.aligned.m16n8k16.row.col.f32.f16.f16.f32 "
        "{%0,%1,%2,%3},{%4,%5,%6,%7},{%8,%9},{%0,%1,%2,%3};"
        : "+f"(c[0]), "+f"(c[1]), "+f"(c[2]), "+f"(c[3])
        : "r"(a[0]), "r"(a[1]), "r"(a[2]), "r"(a[3]), "r"(b[0]), "r"(b[1]));
}

// half4 <-> float4
__device__ __forceinline__ float4 ld_h4(const __half* p) {
    uint2 v = *(const uint2*)p;
    __half2 h0 = *(__half2*)&v.x;
    __half2 h1 = *(__half2*)&v.y;
    float2 f0 = __half22float2(h0);
    float2 f1 = __half22float2(h1);
    return make_float4(f0.x, f0.y, f1.x, f1.y);
}
__device__ __forceinline__ uint2 pack_h4(const float4& f) {
    __half2 h0 = __floats2half2_rn(f.x, f.y);
    __half2 h1 = __floats2half2_rn(f.z, f.w);
    uint2 v;
    v.x = *(uint32_t*)&h0;
    v.y = *(uint32_t*)&h1;
    return v;
}

// ---------------- CSR build ----------------
__global__ void zero_cnt_k() {
    int i = blockIdx.x * blockDim.x + threadIdx.x;
    if (i < NN) g_cnt[i] = 0;
}
__global__ void count_deg_k(const int* __restrict__ ei) {
    int e = blockIdx.x * blockDim.x + threadIdx.x;
    if (e < EE) atomicAdd(&g_cnt[__ldg(ei + EE + e)], 1);
}
__global__ void scan_k() {
    __shared__ int sm[1024];
    int t = threadIdx.x;
    const int CH = (NN + 1023) / 1024;
    int base = t * CH;
    int s = 0;
    for (int i = 0; i < CH; i++) {
        int idx = base + i;
        if (idx < NN) s += g_cnt[idx];
    }
    sm[t] = s;
    __syncthreads();
    for (int off = 1; off < 1024; off <<= 1) {
        int v = 0;
        if (t >= off) v = sm[t - off];
        __syncthreads();
        if (t >= off) sm[t] += v;
        __syncthreads();
    }
    int run = (t == 0) ? 0 : sm[t - 1];
    for (int i = 0; i < CH; i++) {
        int idx = base + i;
        if (idx < NN) {
            g_rowptr[idx] = run;
            run += g_cnt[idx];
        }
    }
    if (t == 1023) g_rowptr[NN] = run;
}
__global__ void fill_col_k(const int* __restrict__ ei) {
    int e = blockIdx.x * blockDim.x + threadIdx.x;
    if (e < EE) {
        int dst = __ldg(ei + EE + e);
        int pos = g_rowptr[dst] + atomicAdd(&g_cnt[dst], 1);
        g_colidx[pos] = __ldg(ei + e);
    }
}

// ---------------- emb -> fp16 ----------------
__global__ void conv_emb_k(const float* __restrict__ emb) {
    size_t i = (size_t)blockIdx.x * blockDim.x + threadIdx.x;
    if (i >= (size_t)NN * KK / 4) return;
    float4 v = *(const float4*)(emb + i * 4);
    *(uint2*)(g_Eh + i * 4) = pack_h4(v);
}

// ---------------- fused aggregation ----------------
__device__ __forceinline__ void store_h4S(int node, int c, const float4& acc) {
    *(uint2*)(g_Sh + (size_t)node * KK + c) = pack_h4(acc);
}

// layer 0: S = E[xi[node]] + sum E[xi[src]]  (E = fp16 emb)
__global__ void agg_emb_k(const int* __restrict__ xi) {
    __shared__ int snb[128];
    int node = blockIdx.x;
    int tid = threadIdx.x;
    int c = tid << 2;
    float4 acc = ld_h4(g_Eh + (size_t)__ldg(xi + node) * KK + c);
    int ps = g_rowptr[node], pe = g_rowptr[node + 1];
    for (int base = ps; base < pe; base += 128) {
        int n = min(128, pe - base);
        __syncthreads();
        if (tid < n) snb[tid] = __ldg(xi + __ldg(g_colidx + base + tid));
        __syncthreads();
        for (int j = 0; j < n; j++) {
            float4 v = ld_h4(g_Eh + (size_t)snb[j] * KK + c);
            acc.x += v.x; acc.y += v.y; acc.z += v.z; acc.w += v.w;
        }
    }
    store_h4S(node, c, acc);
}

// layers 1,2: x = relu(bn(Y)) on the fly; S = x[node] + sum x[src]
__global__ void agg_bn_k() {
    __shared__ int snb[128];
    int node = blockIdx.x;
    int tid = threadIdx.x;
    int c = tid << 2;
    float4 sc = *(const float4*)(g_mv + c);
    float4 sh = *(const float4*)(g_mv + HH + c);
    float4 y = ld_h4(g_Y + (size_t)node * HH + c);
    float4 acc;
    acc.x = fmaxf(fmaf(y.x, sc.x, sh.x), 0.f);
    acc.y = fmaxf(fmaf(y.y, sc.y, sh.y), 0.f);
    acc.z = fmaxf(fmaf(y.z, sc.z, sh.z), 0.f);
    acc.w = fmaxf(fmaf(y.w, sc.w, sh.w), 0.f);
    int ps = g_rowptr[node], pe = g_rowptr[node + 1];
    for (int base = ps; base < pe; base += 128) {
        int n = min(128, pe - base);
        __syncthreads();
        if (tid < n) snb[tid] = __ldg(g_colidx + base + tid);
        __syncthreads();
        for (int j = 0; j < n; j++) {
            float4 v = ld_h4(g_Y + (size_t)snb[j] * HH + c);
            acc.x += fmaxf(fmaf(v.x, sc.x, sh.x), 0.f);
            acc.y += fmaxf(fmaf(v.y, sc.y, sh.y), 0.f);
            acc.z += fmaxf(fmaf(v.z, sc.z, sh.z), 0.f);
            acc.w += fmaxf(fmaf(v.w, sc.w, sh.w), 0.f);
        }
    }
    store_h4S(node, c, acc);
}

// ---------------- BN stats ----------------
__global__ void zero_stats_k() {
    int i = threadIdx.x;
    g_stats[i] = 0.f;
    g_stats[HH + i] = 0.f;
}
#define SROWS 250
__global__ void stats_k() {
    int c = threadIdx.x;
    int r0 = blockIdx.x * SROWS;
    int r1 = min(r0 + SROWS, NN);
    float s0 = 0.f, q0 = 0.f, s1 = 0.f, q1 = 0.f;
    for (int r = r0; r < r1; r++) {
        float v0 = __half2float(g_Y[(size_t)r * HH + c]);
        float v1 = __half2float(g_Y[(size_t)r * HH + c + 256]);
        s0 += v0; q0 += v0 * v0;
        s1 += v1; q1 += v1 * v1;
    }
    atomicAdd(&g_stats[c], s0);
    atomicAdd(&g_stats[HH + c], q0);
    atomicAdd(&g_stats[c + 256], s1);
    atomicAdd(&g_stats[HH + c + 256], q1);
}
__global__ void finalize_k(const float* __restrict__ gam, const float* __restrict__ bet) {
    int c = threadIdx.x;
    float mu = g_stats[c] * (1.f / NN);
    float var = g_stats[HH + c] * (1.f / NN) - mu * mu;
    float sc = rsqrtf(var + BN_EPS) * gam[c];
    g_mv[c] = sc;
    g_mv[HH + c] = bet[c] - mu * sc;
}

// ---------------- weight transpose + fp16 convert ----------------
__global__ void wsplit_k(const float* __restrict__ w, __half* __restrict__ th, int Ndim) {
    __shared__ float t[32][33];
    int bx = blockIdx.x * 32;  // k
    int by = blockIdx.y * 32;  // n
    int x = threadIdx.x, y = threadIdx.y;
#pragma unroll
    for (int i = 0; i < 32; i += 8)
        t[y + i][x] = w[(size_t)(bx + y + i) * Ndim + by + x];
    __syncthreads();
#pragma unroll
    for (int i = 0; i < 32; i += 8)
        th[(size_t)(by + y + i) * KK + bx + x] = __float2half_rn(t[x][y + i]);
}

// ---------------- mma.sync GEMM (BK=32, static 48KB smem, 3-stage) ----------------
__device__ __forceinline__ void load_tiles(
    uint32_t sa, uint32_t sb,
    const __half* __restrict__ A, const __half* __restrict__ W,
    int mBase, int M, int nBase, int kk, int tid)
{
#pragma unroll
    for (int i = 0; i < 2; i++) {
        int idx = i * 256 + tid;
        int row = idx >> 2, cu = idx & 3;
        int grow = mBase + row;
        const char* src = (const char*)(A + (size_t)grow * KK + kk) + cu * 16;
        cpa16(sa + sw64(row * 64 + cu * 16), src, grow < M);
    }
#pragma unroll
    for (int i = 0; i < 2; i++) {
        int idx = i * 256 + tid;
        int row = idx >> 2, cu = idx & 3;
        const char* src = (const char*)(W + (size_t)(nBase + row) * KK + kk) + cu * 16;
        cpa16(sb + sw64(row * 64 + cu * 16), src, true);
    }
}

// MODE 0: bias+relu -> fp16 H ; MODE 1: bias -> fp16 Y ; MODE 2: bias -> fp32 out
template <int MODE>
__global__ void __launch_bounds__(256) gemm_mma(
    const __half* __restrict__ Ah, const __half* __restrict__ Wt,
    const float* __restrict__ bias,
    float* __restrict__ Cf, __half* __restrict__ Ch,
    int M, int Ncols)
{
    __shared__ __align__(1024) uint8_t smem[3 * 16384];  // 3 stages x (A 8K + B 8K)
    uint32_t sbase = smem_u32(smem);

    const int tid = threadIdx.x, lane = tid & 31, wid = tid >> 5;
    const int wm = wid >> 1, wn = wid & 1;
    const int mBase = blockIdx.y * BM;
    const int nBase = blockIdx.x * BNT;

    float acc[2][8][4];
#pragma unroll
    for (int a = 0; a < 2; a++)
#pragma unroll
        for (int b = 0; b < 8; b++)
#pragma unroll
            for (int c = 0; c < 4; c++) acc[a][b][c] = 0.f;

    load_tiles(sbase, sbase + 8192, Ah, Wt, mBase, M, nBase, 0, tid);
    cpa_commit();
    load_tiles(sbase + 16384, sbase + 16384 + 8192, Ah, Wt, mBase, M, nBase, 32, tid);
    cpa_commit();

    for (int kc = 0; kc < NCH; kc++) {
        int buf = kc % 3;
        if (kc + 2 < NCH) {
            int nb = (kc + 2) % 3;
            load_tiles(sbase + nb * 16384, sbase + nb * 16384 + 8192,
                       Ah, Wt, mBase, M, nBase, (kc + 2) * 32, tid);
            cpa_commit();
            cpa_wait<2>();
        } else {
            cpa_wait<0>();
        }
        __syncthreads();

        uint32_t aT = sbase + buf * 16384;
        uint32_t bT = aT + 8192;
#pragma unroll
        for (int k16 = 0; k16 < 2; k16++) {
            uint32_t aF[2][4];
#pragma unroll
            for (int fm = 0; fm < 2; fm++) {
                int row = wm * 32 + fm * 16 + (lane & 15);
                int cu = 2 * k16 + (lane >> 4);
                ldmx4(aF[fm], aT + sw64(row * 64 + cu * 16));
            }
            uint32_t bF[4][4];
#pragma unroll
            for (int g = 0; g < 4; g++) {
                int half = (lane >> 3) & 1;
                int sel = lane >> 4;
                int row = wn * 64 + g * 16 + sel * 8 + (lane & 7);
                int cu = 2 * k16 + half;
                ldmx4(bF[g], bT + sw64(row * 64 + cu * 16));
            }
#pragma unroll
            for (int fm = 0; fm < 2; fm++)
#pragma unroll
                for (int fn = 0; fn < 8; fn++)
                    mma16816(acc[fm][fn], aF[fm], &bF[fn >> 1][(fn & 1) * 2]);
        }
        __syncthreads();
    }

    // ---- epilogue ----
#pragma unroll
    for (int fn = 0; fn < 8; fn++) {
        int col = nBase + wn * 64 + fn * 8 + (lane & 3) * 2;
        float bv0 = __ldg(bias + col);
        float bv1 = __ldg(bias + col + 1);
#pragma unroll
        for (int fm = 0; fm < 2; fm++) {
            int rowb = mBase + wm * 32 + fm * 16 + (lane >> 2);
            float* a = acc[fm][fn];
#pragma unroll
            for (int h = 0; h < 2; h++) {
                int r = rowb + 8 * h;
                if (r < M) {
                    float v0 = a[2 * h] + bv0, v1 = a[2 * h + 1] + bv1;
                    if (MODE == 0) {
                        v0 = fmaxf(v0, 0.f);
                        v1 = fmaxf(v1, 0.f);
                        __half2 hp = __floats2half2_rn(v0, v1);
                        *(__half2*)(Ch + (size_t)r * Ncols + col) = hp;
                    } else if (MODE == 1) {
                        __half2 hp = __floats2half2_rn(v0, v1);
                        *(__half2*)(Ch + (size_t)r * Ncols + col) = hp;
                    } else {
                        float2 o; o.x = v0; o.y = v1;
                        *(float2*)(Cf + (size_t)r * Ncols + col) = o;
                    }
                }
            }
        }
    }
}

// ---------------- driver ----------------
extern "C" void kernel_launch(void* const* d_in, const int* in_sizes, int n_in,
                              void* d_out, int out_size) {
    const int*   xi  = (const int*)d_in[0];
    const int*   ei  = (const int*)d_in[1];
    const float* emb = (const float*)d_in[2];
    const float* w1[3] = {(const float*)d_in[3], (const float*)d_in[9],  (const float*)d_in[15]};
    const float* b1[3] = {(const float*)d_in[4], (const float*)d_in[10], (const float*)d_in[16]};
    const float* w2[3] = {(const float*)d_in[5], (const float*)d_in[11], (const float*)d_in[17]};
    const float* b2[3] = {(const float*)d_in[6], (const float*)d_in[12], (const float*)d_in[18]};
    const float* gam[2] = {(const float*)d_in[7], (const float*)d_in[13]};
    const float* bet[2] = {(const float*)d_in[8], (const float*)d_in[14]};

    __half *pSh, *pHh, *pWh, *pVh, *pYh;
    cudaGetSymbolAddress((void**)&pSh, g_Sh);
    cudaGetSymbolAddress((void**)&pHh, g_Hh);
    cudaGetSymbolAddress((void**)&pWh, g_Wh);
    cudaGetSymbolAddress((void**)&pVh, g_Vh);
    cudaGetSymbolAddress((void**)&pYh, g_Y);

    dim3 tb(32, 8);
    dim3 gw512(KK / 32, 512 / 32);
    dim3 gw256(KK / 32, 256 / 32);

    // weight transposes + emb conversion (independent — front of graph)
    for (int l = 0; l < 3; ++l) {
        wsplit_k<<<gw512, tb>>>(w1[l], pWh + (size_t)l * KK * HH, 512);
        if (l < 2)
            wsplit_k<<<gw512, tb>>>(w2[l], pVh + (size_t)l * KK * HH, 512);
        else
            wsplit_k<<<gw256, tb>>>(w2[2], pVh + (size_t)2 * KK * HH, 256);
    }
    conv_emb_k<<<(NN * KK / 4 + 255) / 256, 256>>>(emb);

    // CSR build
    zero_cnt_k<<<(NN + 255) / 256, 256>>>();
    count_deg_k<<<(EE + 255) / 256, 256>>>(ei);
    scan_k<<<1, 1024>>>();
    zero_cnt_k<<<(NN + 255) / 256, 256>>>();
    fill_col_k<<<(EE + 255) / 256, 256>>>(ei);

    dim3 gg512(512 / BNT, (NN + BM - 1) / BM);
    dim3 gg256(256 / BNT, (NN + BM - 1) / BM);

    for (int l = 0; l < 3; ++l) {
        if (l == 0) agg_emb_k<<<NN, 128>>>(xi);
        else        agg_bn_k<<<NN, 128>>>();

        gemm_mma<0><<<gg512, 256>>>(pSh,
            pWh + (size_t)l * KK * HH, b1[l], nullptr, pHh, NN, 512);

        if (l < 2) {
            gemm_mma<1><<<gg512, 256>>>(pHh,
                pVh + (size_t)l * KK * HH, b2[l], nullptr, pYh, NN, 512);
            zero_stats_k<<<1, HH>>>();
            stats_k<<<(NN + SROWS - 1) / SROWS, 256>>>();
            finalize_k<<<1, HH>>>(gam[l], bet[l]);
        } else {
            gemm_mma<2><<<gg256, 256>>>(pHh,
                pVh + (size_t)2 * KK * HH, b2[2], (float*)d_out, nullptr, NN, 256);
        }
    }
}

// round 12
// speedup vs baseline: 5.0240x; 1.0910x over previous
#include <cuda_runtime.h>
#include <cuda_fp16.h>
#include <stdint.h>

#define NN 50000
#define EE 400000
#define HH 512
#define OO 256
#define KK 512
#define BN_EPS 1e-5f

#define BM 128
#define BNT 128          // N tile
#define NCH 16           // 16 chunks of K=32, single fp16 term

// ---------------- scratch (device globals) ----------------
__device__ __align__(256) __half g_Y[(size_t)NN * HH];           // fp16 pre-BN gemm2 out
__device__ __align__(256) __half g_Eh[(size_t)NN * KK];          // fp16(emb)
__device__ __align__(256) __half g_Sh[(size_t)NN * KK];          // fp16(S)
__device__ __align__(256) __half g_Hh[(size_t)NN * HH];          // fp16(relu(gemm1))
__device__ __align__(256) __half g_Wh[3][KK * HH];               // w1 fp16 [N][K]
__device__ __align__(256) __half g_Vh[3][KK * HH];               // w2 fp16 [N][K]
__device__ int   g_rowptr[NN + 1];
__device__ int   g_cnt[NN];
__device__ int   g_colidx[EE];
__device__ float g_stats[2 * HH];
__device__ float g_mv[2 * HH];

// ---------------- PTX helpers (sm_80-level, sm_100-safe) ----------------
__device__ __forceinline__ uint32_t smem_u32(const void* p) {
    uint32_t a;
    asm("{ .reg .u64 t; cvta.to.shared.u64 t, %1; cvt.u32.u64 %0, t; }" : "=r"(a) : "l"(p));
    return a;
}
__device__ __forceinline__ uint32_t sw64(uint32_t b) { return b ^ ((b >> 3) & 0x30); }

__device__ __forceinline__ void cpa16(uint32_t dst, const void* src, bool pred) {
    int sz = pred ? 16 : 0;
    asm volatile("cp.async.cg.shared.global [%0], [%1], 16, %2;"
                 :: "r"(dst), "l"(src), "r"(sz) : "memory");
}
__device__ __forceinline__ void cpa_commit() {
    asm volatile("cp.async.commit_group;" ::: "memory");
}
template <int N>
__device__ __forceinline__ void cpa_wait() {
    asm volatile("cp.async.wait_group %0;" :: "n"(N) : "memory");
}
__device__ __forceinline__ void ldmx4(uint32_t* r, uint32_t addr) {
    asm volatile("ldmatrix.sync.aligned.m8n8.x4.shared.b16 {%0,%1,%2,%3}, [%4];"
                 : "=r"(r[0]), "=r"(r[1]), "=r"(r[2]), "=r"(r[3]) : "r"(addr));
}
__device__ __forceinline__ void mma16816(float* c, const uint32_t* a, const uint32_t* b) {
    asm volatile(
        "mma.sync.aligned.m16n8k16.row.col.f32.f16.f16.f32 "
        "{%0,%1,%2,%3},{%4,%5,%6,%7},{%8,%9},{%0,%1,%2,%3};"
        : "+f"(c[0]), "+f"(c[1]), "+f"(c[2]), "+f"(c[3])
        : "r"(a[0]), "r"(a[1]), "r"(a[2]), "r"(a[3]), "r"(b[0]), "r"(b[1]));
}

// half4 <-> float4
__device__ __forceinline__ float4 ld_h4(const __half* p) {
    uint2 v = *(const uint2*)p;
    __half2 h0 = *(__half2*)&v.x;
    __half2 h1 = *(__half2*)&v.y;
    float2 f0 = __half22float2(h0);
    float2 f1 = __half22float2(h1);
    return make_float4(f0.x, f0.y, f1.x, f1.y);
}
__device__ __forceinline__ uint2 pack_h4(const float4& f) {
    __half2 h0 = __floats2half2_rn(f.x, f.y);
    __half2 h1 = __floats2half2_rn(f.z, f.w);
    uint2 v;
    v.x = *(uint32_t*)&h0;
    v.y = *(uint32_t*)&h1;
    return v;
}

// ---------------- CSR build ----------------
__global__ void zero_cnt_k() {
    int i = blockIdx.x * blockDim.x + threadIdx.x;
    if (i < NN) g_cnt[i] = 0;
}
__global__ void count_deg_k(const int* __restrict__ ei) {
    int e = blockIdx.x * blockDim.x + threadIdx.x;
    if (e < EE) atomicAdd(&g_cnt[__ldg(ei + EE + e)], 1);
}
__global__ void scan_k() {
    __shared__ int sm[1024];
    int t = threadIdx.x;
    const int CH = (NN + 1023) / 1024;
    int base = t * CH;
    int s = 0;
    for (int i = 0; i < CH; i++) {
        int idx = base + i;
        if (idx < NN) s += g_cnt[idx];
    }
    sm[t] = s;
    __syncthreads();
    for (int off = 1; off < 1024; off <<= 1) {
        int v = 0;
        if (t >= off) v = sm[t - off];
        __syncthreads();
        if (t >= off) sm[t] += v;
        __syncthreads();
    }
    int run = (t == 0) ? 0 : sm[t - 1];
    for (int i = 0; i < CH; i++) {
        int idx = base + i;
        if (idx < NN) {
            g_rowptr[idx] = run;
            run += g_cnt[idx];
        }
    }
    if (t == 1023) g_rowptr[NN] = run;
}
__global__ void fill_col_k(const int* __restrict__ ei) {
    int e = blockIdx.x * blockDim.x + threadIdx.x;
    if (e < EE) {
        int dst = __ldg(ei + EE + e);
        int pos = g_rowptr[dst] + atomicAdd(&g_cnt[dst], 1);
        g_colidx[pos] = __ldg(ei + e);
    }
}

// ---------------- emb -> fp16 ----------------
__global__ void conv_emb_k(const float* __restrict__ emb) {
    size_t i = (size_t)blockIdx.x * blockDim.x + threadIdx.x;
    if (i >= (size_t)NN * KK / 4) return;
    float4 v = *(const float4*)(emb + i * 4);
    *(uint2*)(g_Eh + i * 4) = pack_h4(v);
}

// ---------------- fused aggregation ----------------
__device__ __forceinline__ void store_h4S(int node, int c, const float4& acc) {
    *(uint2*)(g_Sh + (size_t)node * KK + c) = pack_h4(acc);
}

// layer 0: S = E[xi[node]] + sum E[xi[src]]  (E = fp16 emb)
__global__ void agg_emb_k(const int* __restrict__ xi) {
    __shared__ int snb[128];
    int node = blockIdx.x;
    int tid = threadIdx.x;
    int c = tid << 2;
    float4 acc = ld_h4(g_Eh + (size_t)__ldg(xi + node) * KK + c);
    int ps = g_rowptr[node], pe = g_rowptr[node + 1];
    for (int base = ps; base < pe; base += 128) {
        int n = min(128, pe - base);
        __syncthreads();
        if (tid < n) snb[tid] = __ldg(xi + __ldg(g_colidx + base + tid));
        __syncthreads();
        for (int j = 0; j < n; j++) {
            float4 v = ld_h4(g_Eh + (size_t)snb[j] * KK + c);
            acc.x += v.x; acc.y += v.y; acc.z += v.z; acc.w += v.w;
        }
    }
    store_h4S(node, c, acc);
}

// layers 1,2: x = relu(bn(Y)) on the fly; S = x[node] + sum x[src]
__global__ void agg_bn_k() {
    __shared__ int snb[128];
    int node = blockIdx.x;
    int tid = threadIdx.x;
    int c = tid << 2;
    float4 sc = *(const float4*)(g_mv + c);
    float4 sh = *(const float4*)(g_mv + HH + c);
    float4 y = ld_h4(g_Y + (size_t)node * HH + c);
    float4 acc;
    acc.x = fmaxf(fmaf(y.x, sc.x, sh.x), 0.f);
    acc.y = fmaxf(fmaf(y.y, sc.y, sh.y), 0.f);
    acc.z = fmaxf(fmaf(y.z, sc.z, sh.z), 0.f);
    acc.w = fmaxf(fmaf(y.w, sc.w, sh.w), 0.f);
    int ps = g_rowptr[node], pe = g_rowptr[node + 1];
    for (int base = ps; base < pe; base += 128) {
        int n = min(128, pe - base);
        __syncthreads();
        if (tid < n) snb[tid] = __ldg(g_colidx + base + tid);
        __syncthreads();
        for (int j = 0; j < n; j++) {
            float4 v = ld_h4(g_Y + (size_t)snb[j] * HH + c);
            acc.x += fmaxf(fmaf(v.x, sc.x, sh.x), 0.f);
            acc.y += fmaxf(fmaf(v.y, sc.y, sh.y), 0.f);
            acc.z += fmaxf(fmaf(v.z, sc.z, sh.z), 0.f);
            acc.w += fmaxf(fmaf(v.w, sc.w, sh.w), 0.f);
        }
    }
    store_h4S(node, c, acc);
}

// ---------------- BN stats ----------------
__global__ void zero_stats_k() {
    int i = threadIdx.x;
    g_stats[i] = 0.f;
    g_stats[HH + i] = 0.f;
}
#define SROWS 250
__global__ void stats_k() {
    int c = threadIdx.x;
    int r0 = blockIdx.x * SROWS;
    int r1 = min(r0 + SROWS, NN);
    float s0 = 0.f, q0 = 0.f, s1 = 0.f, q1 = 0.f;
    for (int r = r0; r < r1; r++) {
        float v0 = __half2float(g_Y[(size_t)r * HH + c]);
        float v1 = __half2float(g_Y[(size_t)r * HH + c + 256]);
        s0 += v0; q0 += v0 * v0;
        s1 += v1; q1 += v1 * v1;
    }
    atomicAdd(&g_stats[c], s0);
    atomicAdd(&g_stats[HH + c], q0);
    atomicAdd(&g_stats[c + 256], s1);
    atomicAdd(&g_stats[HH + c + 256], q1);
}
__global__ void finalize_k(const float* __restrict__ gam, const float* __restrict__ bet) {
    int c = threadIdx.x;
    float mu = g_stats[c] * (1.f / NN);
    float var = g_stats[HH + c] * (1.f / NN) - mu * mu;
    float sc = rsqrtf(var + BN_EPS) * gam[c];
    g_mv[c] = sc;
    g_mv[HH + c] = bet[c] - mu * sc;
}

// ---------------- weight transpose + fp16 convert ----------------
__global__ void wsplit_k(const float* __restrict__ w, __half* __restrict__ th, int Ndim) {
    __shared__ float t[32][33];
    int bx = blockIdx.x * 32;  // k
    int by = blockIdx.y * 32;  // n
    int x = threadIdx.x, y = threadIdx.y;
#pragma unroll
    for (int i = 0; i < 32; i += 8)
        t[y + i][x] = w[(size_t)(bx + y + i) * Ndim + by + x];
    __syncthreads();
#pragma unroll
    for (int i = 0; i < 32; i += 8)
        th[(size_t)(by + y + i) * KK + bx + x] = __float2half_rn(t[x][y + i]);
}

// ---------------- mma.sync GEMM (BK=32, static 48KB smem, 3-stage, 2 CTAs/SM) ----------------
__device__ __forceinline__ void load_tiles(
    uint32_t sa, uint32_t sb,
    const __half* __restrict__ A, const __half* __restrict__ W,
    int mBase, int M, int nBase, int kk, int tid)
{
#pragma unroll
    for (int i = 0; i < 2; i++) {
        int idx = i * 256 + tid;
        int row = idx >> 2, cu = idx & 3;
        int grow = mBase + row;
        const char* src = (const char*)(A + (size_t)grow * KK + kk) + cu * 16;
        cpa16(sa + sw64(row * 64 + cu * 16), src, grow < M);
    }
#pragma unroll
    for (int i = 0; i < 2; i++) {
        int idx = i * 256 + tid;
        int row = idx >> 2, cu = idx & 3;
        const char* src = (const char*)(W + (size_t)(nBase + row) * KK + kk) + cu * 16;
        cpa16(sb + sw64(row * 64 + cu * 16), src, true);
    }
}

// MODE 0: bias+relu -> fp16 H ; MODE 1: bias -> fp16 Y ; MODE 2: bias -> fp32 out
template <int MODE>
__global__ void __launch_bounds__(256, 2) gemm_mma(
    const __half* __restrict__ Ah, const __half* __restrict__ Wt,
    const float* __restrict__ bias,
    float* __restrict__ Cf, __half* __restrict__ Ch,
    int M, int Ncols)
{
    __shared__ __align__(1024) uint8_t smem[3 * 16384];  // 3 stages x (A 8K + B 8K)
    uint32_t sbase = smem_u32(smem);

    const int tid = threadIdx.x, lane = tid & 31, wid = tid >> 5;
    const int wm = wid >> 1, wn = wid & 1;
    const int mBase = blockIdx.y * BM;
    const int nBase = blockIdx.x * BNT;

    float acc[2][8][4];
#pragma unroll
    for (int a = 0; a < 2; a++)
#pragma unroll
        for (int b = 0; b < 8; b++)
#pragma unroll
            for (int c = 0; c < 4; c++) acc[a][b][c] = 0.f;

    load_tiles(sbase, sbase + 8192, Ah, Wt, mBase, M, nBase, 0, tid);
    cpa_commit();
    load_tiles(sbase + 16384, sbase + 16384 + 8192, Ah, Wt, mBase, M, nBase, 32, tid);
    cpa_commit();

    for (int kc = 0; kc < NCH; kc++) {
        int buf = kc % 3;
        if (kc + 2 < NCH) {
            int nb = (kc + 2) % 3;
            load_tiles(sbase + nb * 16384, sbase + nb * 16384 + 8192,
                       Ah, Wt, mBase, M, nBase, (kc + 2) * 32, tid);
            cpa_commit();
            cpa_wait<2>();
        } else {
            cpa_wait<0>();
        }
        __syncthreads();

        uint32_t aT = sbase + buf * 16384;
        uint32_t bT = aT + 8192;
#pragma unroll
        for (int k16 = 0; k16 < 2; k16++) {
            uint32_t aF[2][4];
#pragma unroll
            for (int fm = 0; fm < 2; fm++) {
                int row = wm * 32 + fm * 16 + (lane & 15);
                int cu = 2 * k16 + (lane >> 4);
                ldmx4(aF[fm], aT + sw64(row * 64 + cu * 16));
            }
            uint32_t bF[4][4];
#pragma unroll
            for (int g = 0; g < 4; g++) {
                int half = (lane >> 3) & 1;
                int sel = lane >> 4;
                int row = wn * 64 + g * 16 + sel * 8 + (lane & 7);
                int cu = 2 * k16 + half;
                ldmx4(bF[g], bT + sw64(row * 64 + cu * 16));
            }
#pragma unroll
            for (int fm = 0; fm < 2; fm++)
#pragma unroll
                for (int fn = 0; fn < 8; fn++)
                    mma16816(acc[fm][fn], aF[fm], &bF[fn >> 1][(fn & 1) * 2]);
        }
        __syncthreads();
    }

    // ---- epilogue ----
#pragma unroll
    for (int fn = 0; fn < 8; fn++) {
        int col = nBase + wn * 64 + fn * 8 + (lane & 3) * 2;
        float bv0 = __ldg(bias + col);
        float bv1 = __ldg(bias + col + 1);
#pragma unroll
        for (int fm = 0; fm < 2; fm++) {
            int rowb = mBase + wm * 32 + fm * 16 + (lane >> 2);
            float* a = acc[fm][fn];
#pragma unroll
            for (int h = 0; h < 2; h++) {
                int r = rowb + 8 * h;
                if (r < M) {
                    float v0 = a[2 * h] + bv0, v1 = a[2 * h + 1] + bv1;
                    if (MODE == 0) {
                        v0 = fmaxf(v0, 0.f);
                        v1 = fmaxf(v1, 0.f);
                        __half2 hp = __floats2half2_rn(v0, v1);
                        *(__half2*)(Ch + (size_t)r * Ncols + col) = hp;
                    } else if (MODE == 1) {
                        __half2 hp = __floats2half2_rn(v0, v1);
                        *(__half2*)(Ch + (size_t)r * Ncols + col) = hp;
                    } else {
                        float2 o; o.x = v0; o.y = v1;
                        *(float2*)(Cf + (size_t)r * Ncols + col) = o;
                    }
                }
            }
        }
    }
}

// ---------------- driver ----------------
extern "C" void kernel_launch(void* const* d_in, const int* in_sizes, int n_in,
                              void* d_out, int out_size) {
    const int*   xi  = (const int*)d_in[0];
    const int*   ei  = (const int*)d_in[1];
    const float* emb = (const float*)d_in[2];
    const float* w1[3] = {(const float*)d_in[3], (const float*)d_in[9],  (const float*)d_in[15]};
    const float* b1[3] = {(const float*)d_in[4], (const float*)d_in[10], (const float*)d_in[16]};
    const float* w2[3] = {(const float*)d_in[5], (const float*)d_in[11], (const float*)d_in[17]};
    const float* b2[3] = {(const float*)d_in[6], (const float*)d_in[12], (const float*)d_in[18]};
    const float* gam[2] = {(const float*)d_in[7], (const float*)d_in[13]};
    const float* bet[2] = {(const float*)d_in[8], (const float*)d_in[14]};

    __half *pSh, *pHh, *pWh, *pVh, *pYh;
    cudaGetSymbolAddress((void**)&pSh, g_Sh);
    cudaGetSymbolAddress((void**)&pHh, g_Hh);
    cudaGetSymbolAddress((void**)&pWh, g_Wh);
    cudaGetSymbolAddress((void**)&pVh, g_Vh);
    cudaGetSymbolAddress((void**)&pYh, g_Y);

    dim3 tb(32, 8);
    dim3 gw512(KK / 32, 512 / 32);
    dim3 gw256(KK / 32, 256 / 32);

    // weight transposes + emb conversion (independent — front of graph)
    for (int l = 0; l < 3; ++l) {
        wsplit_k<<<gw512, tb>>>(w1[l], pWh + (size_t)l * KK * HH, 512);
        if (l < 2)
            wsplit_k<<<gw512, tb>>>(w2[l], pVh + (size_t)l * KK * HH, 512);
        else
            wsplit_k<<<gw256, tb>>>(w2[2], pVh + (size_t)2 * KK * HH, 256);
    }
    conv_emb_k<<<(NN * KK / 4 + 255) / 256, 256>>>(emb);

    // CSR build
    zero_cnt_k<<<(NN + 255) / 256, 256>>>();
    count_deg_k<<<(EE + 255) / 256, 256>>>(ei);
    scan_k<<<1, 1024>>>();
    zero_cnt_k<<<(NN + 255) / 256, 256>>>();
    fill_col_k<<<(EE + 255) / 256, 256>>>(ei);

    dim3 gg512(512 / BNT, (NN + BM - 1) / BM);
    dim3 gg256(256 / BNT, (NN + BM - 1) / BM);

    for (int l = 0; l < 3; ++l) {
        if (l == 0) agg_emb_k<<<NN, 128>>>(xi);
        else        agg_bn_k<<<NN, 128>>>();

        gemm_mma<0><<<gg512, 256>>>(pSh,
            pWh + (size_t)l * KK * HH, b1[l], nullptr, pHh, NN, 512);

        if (l < 2) {
            gemm_mma<1><<<gg512, 256>>>(pHh,
                pVh + (size_t)l * KK * HH, b2[l], nullptr, pYh, NN, 512);
            zero_stats_k<<<1, HH>>>();
            stats_k<<<(NN + SROWS - 1) / SROWS, 256>>>();
            finalize_k<<<1, HH>>>(gam[l], bet[l]);
        } else {
            gemm_mma<2><<<gg256, 256>>>(pHh,
                pVh + (size_t)2 * KK * HH, b2[2], (float*)d_out, nullptr, NN, 256);
        }
    }
}

// round 14
// speedup vs baseline: 5.0480x; 1.0048x over previous
#include <cuda_runtime.h>
#include <cuda_fp16.h>
#include <stdint.h>

#define NN 50000
#define EE 400000
#define HH 512
#define OO 256
#define KK 512
#define BN_EPS 1e-5f

#define BM 128
#define BNT 128          // N tile
#define NCH 16           // 16 chunks of K=32, single fp16 term

// ---------------- scratch (device globals) ----------------
__device__ __align__(256) __half g_Y[(size_t)NN * HH];           // fp16 pre-BN gemm2 out
__device__ __align__(256) __half g_Eh[(size_t)NN * KK];          // fp16(emb)
__device__ __align__(256) __half g_Sh[(size_t)NN * KK];          // fp16(S)
__device__ __align__(256) __half g_Hh[(size_t)NN * HH];          // fp16(relu(gemm1))
__device__ __align__(256) __half g_Wh[3][KK * HH];               // w1 fp16 [N][K]
__device__ __align__(256) __half g_Vh[3][KK * HH];               // w2 fp16 [N][K]
__device__ int   g_rowptr[NN + 1];
__device__ int   g_cnt[NN];
__device__ int   g_colidx[EE];
__device__ float g_stats[2 * HH];
__device__ float g_mv[2 * HH];

// ---------------- PTX helpers (sm_80-level, sm_100-safe) ----------------
__device__ __forceinline__ uint32_t smem_u32(const void* p) {
    uint32_t a;
    asm("{ .reg .u64 t; cvta.to.shared.u64 t, %1; cvt.u32.u64 %0, t; }" : "=r"(a) : "l"(p));
    return a;
}
__device__ __forceinline__ uint32_t sw64(uint32_t b) { return b ^ ((b >> 3) & 0x30); }

__device__ __forceinline__ void cpa16(uint32_t dst, const void* src, bool pred) {
    int sz = pred ? 16 : 0;
    asm volatile("cp.async.cg.shared.global [%0], [%1], 16, %2;"
                 :: "r"(dst), "l"(src), "r"(sz) : "memory");
}
__device__ __forceinline__ void cpa_commit() {
    asm volatile("cp.async.commit_group;" ::: "memory");
}
template <int N>
__device__ __forceinline__ void cpa_wait() {
    asm volatile("cp.async.wait_group %0;" :: "n"(N) : "memory");
}
__device__ __forceinline__ void ldmx4(uint32_t* r, uint32_t addr) {
    asm volatile("ldmatrix.sync.aligned.m8n8.x4.shared.b16 {%0,%1,%2,%3}, [%4];"
                 : "=r"(r[0]), "=r"(r[1]), "=r"(r[2]), "=r"(r[3]) : "r"(addr));
}
__device__ __forceinline__ void mma16816(float* c, const uint32_t* a, const uint32_t* b) {
    asm volatile(
        "mma.sync.aligned.m16n8k16.row.col.f32.f16.f16.f32 "
        "{%0,%1,%2,%3},{%4,%5,%6,%7},{%8,%9},{%0,%1,%2,%3};"
        : "+f"(c[0]), "+f"(c[1]), "+f"(c[2]), "+f"(c[3])
        : "r"(a[0]), "r"(a[1]), "r"(a[2]), "r"(a[3]), "r"(b[0]), "r"(b[1]));
}

// half4 <-> float4
__device__ __forceinline__ float4 ld_h4(const __half* p) {
    uint2 v = *(const uint2*)p;
    __half2 h0 = *(__half2*)&v.x;
    __half2 h1 = *(__half2*)&v.y;
    float2 f0 = __half22float2(h0);
    float2 f1 = __half22float2(h1);
    return make_float4(f0.x, f0.y, f1.x, f1.y);
}
__device__ __forceinline__ uint2 pack_h4(const float4& f) {
    __half2 h0 = __floats2half2_rn(f.x, f.y);
    __half2 h1 = __floats2half2_rn(f.z, f.w);
    uint2 v;
    v.x = *(uint32_t*)&h0;
    v.y = *(uint32_t*)&h1;
    return v;
}

// ---------------- CSR build ----------------
__global__ void zero_cnt_k() {
    int i = blockIdx.x * blockDim.x + threadIdx.x;
    if (i < NN) g_cnt[i] = 0;
}
__global__ void count_deg_k(const int* __restrict__ ei) {
    int e = blockIdx.x * blockDim.x + threadIdx.x;
    if (e < EE) atomicAdd(&g_cnt[__ldg(ei + EE + e)], 1);
}
__global__ void scan_k() {
    __shared__ int sm[1024];
    int t = threadIdx.x;
    const int CH = (NN + 1023) / 1024;
    int base = t * CH;
    int s = 0;
    for (int i = 0; i < CH; i++) {
        int idx = base + i;
        if (idx < NN) s += g_cnt[idx];
    }
    sm[t] = s;
    __syncthreads();
    for (int off = 1; off < 1024; off <<= 1) {
        int v = 0;
        if (t >= off) v = sm[t - off];
        __syncthreads();
        if (t >= off) sm[t] += v;
        __syncthreads();
    }
    int run = (t == 0) ? 0 : sm[t - 1];
    for (int i = 0; i < CH; i++) {
        int idx = base + i;
        if (idx < NN) {
            g_rowptr[idx] = run;
            run += g_cnt[idx];
        }
    }
    if (t == 1023) g_rowptr[NN] = run;
}
__global__ void fill_col_k(const int* __restrict__ ei) {
    int e = blockIdx.x * blockDim.x + threadIdx.x;
    if (e < EE) {
        int dst = __ldg(ei + EE + e);
        int pos = g_rowptr[dst] + atomicAdd(&g_cnt[dst], 1);
        g_colidx[pos] = __ldg(ei + e);
    }
}

// ---------------- emb -> fp16 ----------------
__global__ void conv_emb_k(const float* __restrict__ emb) {
    size_t i = (size_t)blockIdx.x * blockDim.x + threadIdx.x;
    if (i >= (size_t)NN * KK / 4) return;
    float4 v = *(const float4*)(emb + i * 4);
    *(uint2*)(g_Eh + i * 4) = pack_h4(v);
}

// ---------------- fused aggregation ----------------
__device__ __forceinline__ void store_h4S(int node, int c, const float4& acc) {
    *(uint2*)(g_Sh + (size_t)node * KK + c) = pack_h4(acc);
}

// layer 0: S = E[xi[node]] + sum E[xi[src]]  (E = fp16 emb)
__global__ void agg_emb_k(const int* __restrict__ xi) {
    __shared__ int snb[128];
    int node = blockIdx.x;
    int tid = threadIdx.x;
    int c = tid << 2;
    float4 acc = ld_h4(g_Eh + (size_t)__ldg(xi + node) * KK + c);
    float4 acc2 = make_float4(0.f, 0.f, 0.f, 0.f);
    int ps = g_rowptr[node], pe = g_rowptr[node + 1];
    for (int base = ps; base < pe; base += 128) {
        int n = min(128, pe - base);
        __syncthreads();
        if (tid < n) snb[tid] = __ldg(xi + __ldg(g_colidx + base + tid));
        __syncthreads();
        int j = 0;
        for (; j + 1 < n; j += 2) {
            float4 v0 = ld_h4(g_Eh + (size_t)snb[j] * KK + c);
            float4 v1 = ld_h4(g_Eh + (size_t)snb[j + 1] * KK + c);
            acc.x += v0.x; acc.y += v0.y; acc.z += v0.z; acc.w += v0.w;
            acc2.x += v1.x; acc2.y += v1.y; acc2.z += v1.z; acc2.w += v1.w;
        }
        if (j < n) {
            float4 v = ld_h4(g_Eh + (size_t)snb[j] * KK + c);
            acc.x += v.x; acc.y += v.y; acc.z += v.z; acc.w += v.w;
        }
    }
    acc.x += acc2.x; acc.y += acc2.y; acc.z += acc2.z; acc.w += acc2.w;
    store_h4S(node, c, acc);
}

// layers 1,2: x = relu(bn(Y)) on the fly; S = x[node] + sum x[src]
__global__ void agg_bn_k() {
    __shared__ int snb[128];
    int node = blockIdx.x;
    int tid = threadIdx.x;
    int c = tid << 2;
    float4 sc = *(const float4*)(g_mv + c);
    float4 sh = *(const float4*)(g_mv + HH + c);
    float4 y = ld_h4(g_Y + (size_t)node * HH + c);
    float4 acc;
    acc.x = fmaxf(fmaf(y.x, sc.x, sh.x), 0.f);
    acc.y = fmaxf(fmaf(y.y, sc.y, sh.y), 0.f);
    acc.z = fmaxf(fmaf(y.z, sc.z, sh.z), 0.f);
    acc.w = fmaxf(fmaf(y.w, sc.w, sh.w), 0.f);
    float4 acc2 = make_float4(0.f, 0.f, 0.f, 0.f);
    int ps = g_rowptr[node], pe = g_rowptr[node + 1];
    for (int base = ps; base < pe; base += 128) {
        int n = min(128, pe - base);
        __syncthreads();
        if (tid < n) snb[tid] = __ldg(g_colidx + base + tid);
        __syncthreads();
        int j = 0;
        for (; j + 1 < n; j += 2) {
            float4 v0 = ld_h4(g_Y + (size_t)snb[j] * HH + c);
            float4 v1 = ld_h4(g_Y + (size_t)snb[j + 1] * HH + c);
            acc.x += fmaxf(fmaf(v0.x, sc.x, sh.x), 0.f);
            acc.y += fmaxf(fmaf(v0.y, sc.y, sh.y), 0.f);
            acc.z += fmaxf(fmaf(v0.z, sc.z, sh.z), 0.f);
            acc.w += fmaxf(fmaf(v0.w, sc.w, sh.w), 0.f);
            acc2.x += fmaxf(fmaf(v1.x, sc.x, sh.x), 0.f);
            acc2.y += fmaxf(fmaf(v1.y, sc.y, sh.y), 0.f);
            acc2.z += fmaxf(fmaf(v1.z, sc.z, sh.z), 0.f);
            acc2.w += fmaxf(fmaf(v1.w, sc.w, sh.w), 0.f);
        }
        if (j < n) {
            float4 v = ld_h4(g_Y + (size_t)snb[j] * HH + c);
            acc.x += fmaxf(fmaf(v.x, sc.x, sh.x), 0.f);
            acc.y += fmaxf(fmaf(v.y, sc.y, sh.y), 0.f);
            acc.z += fmaxf(fmaf(v.z, sc.z, sh.z), 0.f);
            acc.w += fmaxf(fmaf(v.w, sc.w, sh.w), 0.f);
        }
    }
    acc.x += acc2.x; acc.y += acc2.y; acc.z += acc2.z; acc.w += acc2.w;
    store_h4S(node, c, acc);
}

// ---------------- BN stats finalize ----------------
__global__ void zero_stats_k() {
    int i = threadIdx.x;
    g_stats[i] = 0.f;
    g_stats[HH + i] = 0.f;
}
__global__ void finalize_k(const float* __restrict__ gam, const float* __restrict__ bet) {
    int c = threadIdx.x;
    float mu = g_stats[c] * (1.f / NN);
    float var = g_stats[HH + c] * (1.f / NN) - mu * mu;
    float sc = rsqrtf(var + BN_EPS) * gam[c];
    g_mv[c] = sc;
    g_mv[HH + c] = bet[c] - mu * sc;
}

// ---------------- weight transpose + fp16 convert ----------------
__global__ void wsplit_k(const float* __restrict__ w, __half* __restrict__ th, int Ndim) {
    __shared__ float t[32][33];
    int bx = blockIdx.x * 32;  // k
    int by = blockIdx.y * 32;  // n
    int x = threadIdx.x, y = threadIdx.y;
#pragma unroll
    for (int i = 0; i < 32; i += 8)
        t[y + i][x] = w[(size_t)(bx + y + i) * Ndim + by + x];
    __syncthreads();
#pragma unroll
    for (int i = 0; i < 32; i += 8)
        th[(size_t)(by + y + i) * KK + bx + x] = __float2half_rn(t[x][y + i]);
}

// ---------------- mma.sync GEMM (BK=32, static 48KB smem, 3-stage, 2 CTAs/SM) ----------------
__device__ __forceinline__ void load_tiles(
    uint32_t sa, uint32_t sb,
    const __half* __restrict__ A, const __half* __restrict__ W,
    int mBase, int M, int nBase, int kk, int tid)
{
#pragma unroll
    for (int i = 0; i < 2; i++) {
        int idx = i * 256 + tid;
        int row = idx >> 2, cu = idx & 3;
        int grow = mBase + row;
        const char* src = (const char*)(A + (size_t)grow * KK + kk) + cu * 16;
        cpa16(sa + sw64(row * 64 + cu * 16), src, grow < M);
    }
#pragma unroll
    for (int i = 0; i < 2; i++) {
        int idx = i * 256 + tid;
        int row = idx >> 2, cu = idx & 3;
        const char* src = (const char*)(W + (size_t)(nBase + row) * KK + kk) + cu * 16;
        cpa16(sb + sw64(row * 64 + cu * 16), src, true);
    }
}

// MODE 0: bias+relu -> fp16 H ; MODE 1: bias -> fp16 Y + fused BN stats ; MODE 2: bias -> fp32 out
template <int MODE>
__global__ void __launch_bounds__(256, 2) gemm_mma(
    const __half* __restrict__ Ah, const __half* __restrict__ Wt,
    const float* __restrict__ bias,
    float* __restrict__ Cf, __half* __restrict__ Ch,
    int M, int Ncols)
{
    __shared__ __align__(1024) uint8_t smem[3 * 16384];  // 3 stages x (A 8K + B 8K)
    uint32_t sbase = smem_u32(smem);

    const int tid = threadIdx.x, lane = tid & 31, wid = tid >> 5;
    const int wm = wid >> 1, wn = wid & 1;
    const int mBase = blockIdx.y * BM;
    const int nBase = blockIdx.x * BNT;

    float acc[2][8][4];
#pragma unroll
    for (int a = 0; a < 2; a++)
#pragma unroll
        for (int b = 0; b < 8; b++)
#pragma unroll
            for (int c = 0; c < 4; c++) acc[a][b][c] = 0.f;

    load_tiles(sbase, sbase + 8192, Ah, Wt, mBase, M, nBase, 0, tid);
    cpa_commit();
    load_tiles(sbase + 16384, sbase + 16384 + 8192, Ah, Wt, mBase, M, nBase, 32, tid);
    cpa_commit();

    for (int kc = 0; kc < NCH; kc++) {
        int buf = kc % 3;
        if (kc + 1 < NCH) cpa_wait<1>();
        else              cpa_wait<0>();
        __syncthreads();
        // prefetch kc+2 into buffer (kc+2)%3 == (kc-1)%3; top sync proved all
        // warps finished reading it during chunk kc-1.
        if (kc + 2 < NCH) {
            int nb = (kc + 2) % 3;
            load_tiles(sbase + nb * 16384, sbase + nb * 16384 + 8192,
                       Ah, Wt, mBase, M, nBase, (kc + 2) * 32, tid);
            cpa_commit();
        }

        uint32_t aT = sbase + buf * 16384;
        uint32_t bT = aT + 8192;
#pragma unroll
        for (int k16 = 0; k16 < 2; k16++) {
            uint32_t aF[2][4];
#pragma unroll
            for (int fm = 0; fm < 2; fm++) {
                int row = wm * 32 + fm * 16 + (lane & 15);
                int cu = 2 * k16 + (lane >> 4);
                ldmx4(aF[fm], aT + sw64(row * 64 + cu * 16));
            }
            uint32_t bF[4][4];
#pragma unroll
            for (int g = 0; g < 4; g++) {
                int half = (lane >> 3) & 1;
                int sel = lane >> 4;
                int row = wn * 64 + g * 16 + sel * 8 + (lane & 7);
                int cu = 2 * k16 + half;
                ldmx4(bF[g], bT + sw64(row * 64 + cu * 16));
            }
#pragma unroll
            for (int fm = 0; fm < 2; fm++)
#pragma unroll
                for (int fn = 0; fn < 8; fn++)
                    mma16816(acc[fm][fn], aF[fm], &bF[fn >> 1][(fn & 1) * 2]);
        }
    }

    // ---- epilogue ----
    float* ss = (float*)smem;  // MODE 1: [0:128] col sums, [128:256] col sumsq
    if (MODE == 1) {
        __syncthreads();       // smem tiles fully consumed (fragments in regs)
        if (tid < 128) { ss[tid] = 0.f; ss[128 + tid] = 0.f; }
        __syncthreads();
    }

#pragma unroll
    for (int fn = 0; fn < 8; fn++) {
        int col = nBase + wn * 64 + fn * 8 + (lane & 3) * 2;
        float bv0 = __ldg(bias + col);
        float bv1 = __ldg(bias + col + 1);
        float ls0 = 0.f, ls1 = 0.f, lq0 = 0.f, lq1 = 0.f;
#pragma unroll
        for (int fm = 0; fm < 2; fm++) {
            int rowb = mBase + wm * 32 + fm * 16 + (lane >> 2);
            float* a = acc[fm][fn];
#pragma unroll
            for (int h = 0; h < 2; h++) {
                int r = rowb + 8 * h;
                if (r < M) {
                    float v0 = a[2 * h] + bv0, v1 = a[2 * h + 1] + bv1;
                    if (MODE == 0) {
                        v0 = fmaxf(v0, 0.f);
                        v1 = fmaxf(v1, 0.f);
                        __half2 hp = __floats2half2_rn(v0, v1);
                        *(__half2*)(Ch + (size_t)r * Ncols + col) = hp;
                    } else if (MODE == 1) {
                        __half2 hp = __floats2half2_rn(v0, v1);
                        *(__half2*)(Ch + (size_t)r * Ncols + col) = hp;
                        ls0 += v0; lq0 += v0 * v0;
                        ls1 += v1; lq1 += v1 * v1;
                    } else {
                        float2 o; o.x = v0; o.y = v1;
                        *(float2*)(Cf + (size_t)r * Ncols + col) = o;
                    }
                }
            }
        }
        if (MODE == 1) {
            // reduce over the 8 lanes sharing this col (stride-4 lane groups)
#pragma unroll
            for (int o = 4; o < 32; o <<= 1) {
                ls0 += __shfl_down_sync(0xffffffffu, ls0, o);
                ls1 += __shfl_down_sync(0xffffffffu, ls1, o);
                lq0 += __shfl_down_sync(0xffffffffu, lq0, o);
                lq1 += __shfl_down_sync(0xffffffffu, lq1, o);
            }
            if (lane < 4) {
                int lc = wn * 64 + fn * 8 + lane * 2;
                atomicAdd(&ss[lc], ls0);
                atomicAdd(&ss[lc + 1], ls1);
                atomicAdd(&ss[128 + lc], lq0);
                atomicAdd(&ss[128 + lc + 1], lq1);
            }
        }
    }

    if (MODE == 1) {
        __syncthreads();
        if (tid < 128) {
            atomicAdd(&g_stats[nBase + tid], ss[tid]);
            atomicAdd(&g_stats[HH + nBase + tid], ss[128 + tid]);
        }
    }
}

// ---------------- driver ----------------
extern "C" void kernel_launch(void* const* d_in, const int* in_sizes, int n_in,
                              void* d_out, int out_size) {
    const int*   xi  = (const int*)d_in[0];
    const int*   ei  = (const int*)d_in[1];
    const float* emb = (const float*)d_in[2];
    const float* w1[3] = {(const float*)d_in[3], (const float*)d_in[9],  (const float*)d_in[15]};
    const float* b1[3] = {(const float*)d_in[4], (const float*)d_in[10], (const float*)d_in[16]};
    const float* w2[3] = {(const float*)d_in[5], (const float*)d_in[11], (const float*)d_in[17]};
    const float* b2[3] = {(const float*)d_in[6], (const float*)d_in[12], (const float*)d_in[18]};
    const float* gam[2] = {(const float*)d_in[7], (const float*)d_in[13]};
    const float* bet[2] = {(const float*)d_in[8], (const float*)d_in[14]};

    __half *pSh, *pHh, *pWh, *pVh, *pYh;
    cudaGetSymbolAddress((void**)&pSh, g_Sh);
    cudaGetSymbolAddress((void**)&pHh, g_Hh);
    cudaGetSymbolAddress((void**)&pWh, g_Wh);
    cudaGetSymbolAddress((void**)&pVh, g_Vh);
    cudaGetSymbolAddress((void**)&pYh, g_Y);

    dim3 tb(32, 8);
    dim3 gw512(KK / 32, 512 / 32);
    dim3 gw256(KK / 32, 256 / 32);

    // weight transposes + emb conversion (independent — front of graph)
    for (int l = 0; l < 3; ++l) {
        wsplit_k<<<gw512, tb>>>(w1[l], pWh + (size_t)l * KK * HH, 512);
        if (l < 2)
            wsplit_k<<<gw512, tb>>>(w2[l], pVh + (size_t)l * KK * HH, 512);
        else
            wsplit_k<<<gw256, tb>>>(w2[2], pVh + (size_t)2 * KK * HH, 256);
    }
    conv_emb_k<<<(NN * KK / 4 + 255) / 256, 256>>>(emb);

    // CSR build
    zero_cnt_k<<<(NN + 255) / 256, 256>>>();
    count_deg_k<<<(EE + 255) / 256, 256>>>(ei);
    scan_k<<<1, 1024>>>();
    zero_cnt_k<<<(NN + 255) / 256, 256>>>();
    fill_col_k<<<(EE + 255) / 256, 256>>>(ei);

    dim3 gg512(512 / BNT, (NN + BM - 1) / BM);
    dim3 gg256(256 / BNT, (NN + BM - 1) / BM);

    for (int l = 0; l < 3; ++l) {
        if (l == 0) agg_emb_k<<<NN, 128>>>(xi);
        else        agg_bn_k<<<NN, 128>>>();

        gemm_mma<0><<<gg512, 256>>>(pSh,
            pWh + (size_t)l * KK * HH, b1[l], nullptr, pHh, NN, 512);

        if (l < 2) {
            zero_stats_k<<<1, HH>>>();
            gemm_mma<1><<<gg512, 256>>>(pHh,
                pVh + (size_t)l * KK * HH, b2[l], nullptr, pYh, NN, 512);
            finalize_k<<<1, HH>>>(gam[l], bet[l]);
        } else {
            gemm_mma<2><<<gg256, 256>>>(pHh,
                pVh + (size_t)2 * KK * HH, b2[2], (float*)d_out, nullptr, NN, 256);
        }
    }
}